// round 7
// baseline (speedup 1.0000x reference)
#include <cuda_runtime.h>

#define H    64
#define G    256
#define F    5
#define BS   28      // samples per block; grid=147 -> 1 CTA/SM, single wave
#define SG   4       // sample subgroups (one per tid>>6)
#define SPG  7       // samples per subgroup
#define TPB  256
#define RB   128

typedef unsigned long long ull;

__device__ float g_rank_part[RB];
__device__ float g_reg_part[2];

__device__ __forceinline__ float tanh_hw(float x) {
    float y;
    asm("tanh.approx.f32 %0, %1;" : "=f"(y) : "f"(x));
    return y;
}
__device__ __forceinline__ float sig_hw(float x) {
    return fmaf(tanh_hw(0.5f * x), 0.5f, 0.5f);
}

// packed dual-FMA (sm_103a FFMA2), lanes = (even-k, odd-k) partials
__device__ __forceinline__ ull fma2(ull a, ull b, ull c) {
    ull d;
    asm("fma.rn.f32x2 %0, %1, %2, %3;" : "=l"(d) : "l"(a), "l"(b), "l"(c));
    return d;
}
__device__ __forceinline__ ull pack2(float lo, float hi) {
    return (ull)__float_as_uint(lo) | ((ull)__float_as_uint(hi) << 32);
}
__device__ __forceinline__ float f2lo(ull v) { return __uint_as_float((unsigned)v); }
__device__ __forceinline__ float f2hi(ull v) { return __uint_as_float((unsigned)(v >> 32)); }

__global__ __launch_bounds__(TPB, 1)
void lstm_kernel(const float* __restrict__ feature,
                 const float* __restrict__ Wih, const float* __restrict__ Whh,
                 const float* __restrict__ bih, const float* __restrict__ bhh,
                 const float* __restrict__ Wd,  const float* __restrict__ bd,
                 float* __restrict__ pred, int N, int T)
{
    const int tid = threadIdx.x;
    const int j   = tid & 63;        // hidden unit
    const int sg  = tid >> 6;        // sample subgroup (0..3)
    const int n0  = blockIdx.x * BS;

    // This thread owns gate rows j (i), 64+j (f), 128+j (g), 192+j (o).
    // Whh rows k-packed into f32x2: 4 x 32 ull = 128 regs.
    ull wk[4][H / 2];
    float wx[4][F];
    float bb[4];
#pragma unroll
    for (int r4 = 0; r4 < 4; r4++) {
        const int row = r4 * H + j;
        const float4* w4 = (const float4*)(Whh + row * H);
#pragma unroll
        for (int q = 0; q < H / 4; q++) {
            float4 v = w4[q];
            wk[r4][2 * q + 0] = pack2(v.x, v.y);
            wk[r4][2 * q + 1] = pack2(v.z, v.w);
        }
#pragma unroll
        for (int f = 0; f < F; f++) wx[r4][f] = Wih[row * F + f];
        bb[r4] = bih[row] + bhh[row];
    }

    __shared__ __align__(16) float h_sm[2][BS][H];
    __shared__ __align__(16) float x_sm[2][BS][8];   // padded to 8 for float4

    // zero-init
    for (int i = tid; i < 2 * BS * H; i += TPB)
        ((float*)h_sm)[i] = 0.f;
    for (int i = tid; i < 2 * BS * 8; i += TPB)
        ((float*)x_sm)[i] = 0.f;
    __syncthreads();
    if (tid < BS * F) {
        int s = tid / F, f = tid % F;
        if (n0 + s < N) x_sm[0][s][f] = feature[(size_t)(n0 + s) * T * F + f];
    }
    __syncthreads();

    float c_reg[SPG];
#pragma unroll
    for (int i = 0; i < SPG; i++) c_reg[i] = 0.f;

    for (int t = 0; t < T; t++) {
        const int cur = t & 1, nxt = cur ^ 1;

#pragma unroll
        for (int i = 0; i < SPG; i++) {
            const int s = sg * SPG + i;

            // 4 independent k-packed dot chains (one per gate)
            ull a0 = pack2(bb[0], 0.f);
            ull a1 = pack2(bb[1], 0.f);
            ull a2 = pack2(bb[2], 0.f);
            ull a3 = pack2(bb[3], 0.f);
            const ulonglong2* h2 = (const ulonglong2*)h_sm[cur][s];  // uniform -> broadcast
#pragma unroll
            for (int q = 0; q < H / 4; q++) {
                ulonglong2 hv = h2[q];
                a0 = fma2(wk[0][2 * q], hv.x, a0);
                a1 = fma2(wk[1][2 * q], hv.x, a1);
                a2 = fma2(wk[2][2 * q], hv.x, a2);
                a3 = fma2(wk[3][2 * q], hv.x, a3);
                a0 = fma2(wk[0][2 * q + 1], hv.y, a0);
                a1 = fma2(wk[1][2 * q + 1], hv.y, a1);
                a2 = fma2(wk[2][2 * q + 1], hv.y, a2);
                a3 = fma2(wk[3][2 * q + 1], hv.y, a3);
            }
            float g0 = f2lo(a0) + f2hi(a0);
            float g1 = f2lo(a1) + f2hi(a1);
            float g2 = f2lo(a2) + f2hi(a2);
            float g3 = f2lo(a3) + f2hi(a3);

            // input-projection terms
            const float4 xv = *(const float4*)x_sm[cur][s];
            const float  x4 = x_sm[cur][s][4];
            g0 = fmaf(wx[0][0], xv.x, g0); g1 = fmaf(wx[1][0], xv.x, g1);
            g2 = fmaf(wx[2][0], xv.x, g2); g3 = fmaf(wx[3][0], xv.x, g3);
            g0 = fmaf(wx[0][1], xv.y, g0); g1 = fmaf(wx[1][1], xv.y, g1);
            g2 = fmaf(wx[2][1], xv.y, g2); g3 = fmaf(wx[3][1], xv.y, g3);
            g0 = fmaf(wx[0][2], xv.z, g0); g1 = fmaf(wx[1][2], xv.z, g1);
            g2 = fmaf(wx[2][2], xv.z, g2); g3 = fmaf(wx[3][2], xv.z, g3);
            g0 = fmaf(wx[0][3], xv.w, g0); g1 = fmaf(wx[1][3], xv.w, g1);
            g2 = fmaf(wx[2][3], xv.w, g2); g3 = fmaf(wx[3][3], xv.w, g3);
            g0 = fmaf(wx[0][4], x4, g0);   g1 = fmaf(wx[1][4], x4, g1);
            g2 = fmaf(wx[2][4], x4, g2);   g3 = fmaf(wx[3][4], x4, g3);

            // fused cell update (gate order i,f,g,o)
            float ig = sig_hw(g0);
            float fg = sig_hw(g1);
            float gg = tanh_hw(g2);
            float og = sig_hw(g3);
            float c  = fg * c_reg[i] + ig * gg;
            c_reg[i] = c;
            h_sm[nxt][s][j] = og * tanh_hw(c);
        }

        // prefetch x for t+1 into the nxt parity buffer
        if (t + 1 < T && tid < BS * F) {
            int s = tid / F, f = tid % F;
            if (n0 + s < N)
                x_sm[nxt][s][f] =
                    feature[(size_t)(n0 + s) * T * F + (size_t)(t + 1) * F + f];
        }
        __syncthreads();
    }

    // ---- head: pred = leaky_relu(h . Wd + bd, 0.2)
    const int fin = T & 1;
    int w = tid >> 5, lane = tid & 31;
    for (int s = w; s < BS; s += TPB / 32) {
        if (n0 + s < N) {
            float p = h_sm[fin][s][lane] * Wd[lane]
                    + h_sm[fin][s][lane + 32] * Wd[lane + 32];
#pragma unroll
            for (int off = 16; off; off >>= 1) p += __shfl_down_sync(0xffffffffu, p, off);
            if (lane == 0) {
                p += bd[0];
                p = p > 0.f ? p : 0.2f * p;
                pred[n0 + s] = p;
            }
        }
    }
}

// Pairwise rank loss partials + masked MSE partials (deterministic, no atomics).
__global__ void pair_kernel(const float* __restrict__ pred, const float* __restrict__ ret,
                            const unsigned* __restrict__ mask, int N)
{
    __shared__ float p_sm[4096];
    __shared__ float t_sm[4096];
    __shared__ unsigned char m_sm[4096];
    __shared__ float red[256];
    const int tid = threadIdx.x;

    for (int n = tid; n < N; n += blockDim.x) {
        p_sm[n] = pred[n];
        t_sm[n] = ret[n];
        m_sm[n] = (mask[n] != 0u) ? 1 : 0;
    }
    __syncthreads();

    float rsum = 0.f;
    for (int i = blockIdx.x; i < N; i += gridDim.x) {
        if (!m_sm[i]) continue;
        float pi = p_sm[i], gi = t_sm[i];
        for (int jj = tid; jj < N; jj += blockDim.x) {
            float v = -(p_sm[jj] - pi) * (t_sm[jj] - gi);
            v = fmaxf(v, 0.f);
            rsum += v * (float)m_sm[jj];
        }
    }
    red[tid] = rsum;
    __syncthreads();
    for (int s = 128; s; s >>= 1) { if (tid < s) red[tid] += red[tid + s]; __syncthreads(); }
    if (tid == 0) g_rank_part[blockIdx.x] = red[0];

    if (blockIdx.x == 0) {
        float ssq = 0.f, sm = 0.f;
        for (int n = tid; n < N; n += blockDim.x) {
            float m = (float)m_sm[n];
            float d = p_sm[n] - t_sm[n];
            ssq += d * d * m;
            sm  += m;
        }
        __syncthreads();
        red[tid] = ssq; __syncthreads();
        for (int s = 128; s; s >>= 1) { if (tid < s) red[tid] += red[tid + s]; __syncthreads(); }
        if (tid == 0) g_reg_part[0] = red[0];
        __syncthreads();
        red[tid] = sm; __syncthreads();
        for (int s = 128; s; s >>= 1) { if (tid < s) red[tid] += red[tid + s]; __syncthreads(); }
        if (tid == 0) g_reg_part[1] = red[0];
    }
}

__global__ void finalize_kernel(float* __restrict__ out, int N)
{
    if (threadIdx.x == 0 && blockIdx.x == 0) {
        float srank = 0.f;
        for (int b = 0; b < RB; b++) srank += g_rank_part[b];
        float reg  = g_reg_part[0] / (g_reg_part[1] + 1e-8f);
        float rank = srank / ((float)N * (float)N);
        out[N]     = reg + rank;
        out[N + 1] = reg;
        out[N + 2] = rank;
    }
}

extern "C" void kernel_launch(void* const* d_in, const int* in_sizes, int n_in,
                              void* d_out, int out_size)
{
    const float*    feature = (const float*)d_in[0];
    const float*    ret     = (const float*)d_in[1];
    const unsigned* mask    = (const unsigned*)d_in[2];
    const float*    Wih     = (const float*)d_in[3];
    const float*    Whh     = (const float*)d_in[4];
    const float*    bih     = (const float*)d_in[5];
    const float*    bhh     = (const float*)d_in[6];
    const float*    Wd      = (const float*)d_in[7];
    const float*    bd      = (const float*)d_in[8];
    float* out = (float*)d_out;

    const int N = in_sizes[1];                 // 4096
    const int T = in_sizes[0] / (N * F);       // 512

    const int grid = (N + BS - 1) / BS;        // 147
    lstm_kernel<<<grid, TPB>>>(feature, Wih, Whh, bih, bhh, Wd, bd, out, N, T);
    pair_kernel<<<RB, 256>>>(out, ret, mask, N);
    finalize_kernel<<<1, 32>>>(out, N);
}

// round 9
// speedup vs baseline: 1.5874x; 1.5874x over previous
#include <cuda_runtime.h>

#define H    64
#define G    256
#define F    5
#define BS   28      // samples per block; grid=147 -> 1 CTA/SM, single wave
#define HS   14      // samples per thread-half
#define TPB  256
#define RB   128
#define CPT  (BS * H / TPB)   // 7 cells/thread in phase 2

typedef unsigned long long ull;

__device__ float g_rank_part[RB];
__device__ float g_reg_part[2];

__device__ __forceinline__ float tanh_hw(float x) {
    float y;
    asm("tanh.approx.f32 %0, %1;" : "=f"(y) : "f"(x));
    return y;
}
__device__ __forceinline__ float sig_hw(float x) {
    return fmaf(tanh_hw(0.5f * x), 0.5f, 0.5f);
}

// packed dual-FMA (sm_103a FFMA2), lanes = (even-k, odd-k) partials
__device__ __forceinline__ ull fma2(ull a, ull b, ull c) {
    ull d;
    asm("fma.rn.f32x2 %0, %1, %2, %3;" : "=l"(d) : "l"(a), "l"(b), "l"(c));
    return d;
}
__device__ __forceinline__ ull pack2(float lo, float hi) {
    return (ull)__float_as_uint(lo) | ((ull)__float_as_uint(hi) << 32);
}
__device__ __forceinline__ float f2lo(ull v) { return __uint_as_float((unsigned)v); }
__device__ __forceinline__ float f2hi(ull v) { return __uint_as_float((unsigned)(v >> 32)); }

__global__ __launch_bounds__(TPB, 1)
void lstm_kernel(const float* __restrict__ feature,
                 const float* __restrict__ Wih, const float* __restrict__ Whh,
                 const float* __restrict__ bih, const float* __restrict__ bhh,
                 const float* __restrict__ Wd,  const float* __restrict__ bd,
                 float* __restrict__ pred, int N, int T)
{
    const int tid  = threadIdx.x;
    const int half = tid >> 7;           // 0: samples 0..13, 1: samples 14..27
    const int rr   = tid & 127;
    const int r0   = 2 * rr, r1 = 2 * rr + 1;   // this thread's gate rows
    const int n0   = blockIdx.x * BS;
    const int sb   = half * HS;          // first sample of this half

    // Two Whh rows resident, k-packed f32x2 (128 regs)
    ull wa[H / 2], wb[H / 2];
    {
        const float4* pa = (const float4*)(Whh + r0 * H);
        const float4* pb = (const float4*)(Whh + r1 * H);
#pragma unroll
        for (int q = 0; q < H / 4; q++) {
            float4 va = pa[q], vb = pb[q];
            wa[2 * q]     = pack2(va.x, va.y);
            wa[2 * q + 1] = pack2(va.z, va.w);
            wb[2 * q]     = pack2(vb.x, vb.y);
            wb[2 * q + 1] = pack2(vb.z, vb.w);
        }
    }
    float wx0[F], wx1[F];
#pragma unroll
    for (int f = 0; f < F; f++) { wx0[f] = Wih[r0 * F + f]; wx1[f] = Wih[r1 * F + f]; }
    const float bias0 = bih[r0] + bhh[r0];
    const float bias1 = bih[r1] + bhh[r1];

    __shared__ __align__(16) float h_sm[BS][H];
    __shared__ float g_sm[BS][G];
    __shared__ __align__(16) float x_sm[2][BS][8];   // padded rows for float4

    float c_reg[CPT];
#pragma unroll
    for (int u = 0; u < CPT; u++) {
        c_reg[u] = 0.f;
        int idx = tid + TPB * u;
        h_sm[idx >> 6][idx & 63] = 0.f;
    }
    for (int i = tid; i < 2 * BS * 8; i += TPB) ((float*)x_sm)[i] = 0.f;
    __syncthreads();
    if (tid < BS * F) {
        int s = tid / F, f = tid % F;
        if (n0 + s < N) x_sm[0][s][f] = feature[(size_t)(n0 + s) * T * F + f];
    }
    __syncthreads();

    for (int t = 0; t < T; t++) {
        const int buf = t & 1;

        // ---- phase 1: two gate rows, this half's 14 samples
        // one LDS.128 of h feeds 4 FFMA2 (2 rows x 2 k)
#pragma unroll 2
        for (int i = 0; i < HS; i++) {
            const int s = sb + i;
            ull a0 = pack2(bias0, 0.f);
            ull a1 = pack2(bias1, 0.f);
            const ulonglong2* h2 = (const ulonglong2*)h_sm[s];   // uniform -> broadcast
#pragma unroll
            for (int q = 0; q < H / 4; q++) {
                ulonglong2 hv = h2[q];
                a0 = fma2(wa[2 * q],     hv.x, a0);
                a1 = fma2(wb[2 * q],     hv.x, a1);
                a0 = fma2(wa[2 * q + 1], hv.y, a0);
                a1 = fma2(wb[2 * q + 1], hv.y, a1);
            }
            float v0 = f2lo(a0) + f2hi(a0);
            float v1 = f2lo(a1) + f2hi(a1);
            const float4 xv = *(const float4*)x_sm[buf][s];
            const float  x4 = x_sm[buf][s][4];
            v0 = fmaf(wx0[0], xv.x, v0); v1 = fmaf(wx1[0], xv.x, v1);
            v0 = fmaf(wx0[1], xv.y, v0); v1 = fmaf(wx1[1], xv.y, v1);
            v0 = fmaf(wx0[2], xv.z, v0); v1 = fmaf(wx1[2], xv.z, v1);
            v0 = fmaf(wx0[3], xv.w, v0); v1 = fmaf(wx1[3], xv.w, v1);
            v0 = fmaf(wx0[4], x4,   v0); v1 = fmaf(wx1[4], x4,   v1);
            *(float2*)&g_sm[s][r0] = make_float2(v0, v1);        // STS.64
        }
        __syncthreads();

        // ---- prefetch x for t+1
        if (t + 1 < T && tid < BS * F) {
            int s = tid / F, f = tid % F;
            if (n0 + s < N)
                x_sm[buf ^ 1][s][f] =
                    feature[(size_t)(n0 + s) * T * F + (size_t)(t + 1) * F + f];
        }

        // ---- phase 2: LSTM cell update (gate order i,f,g,o), 7 cells/thread
#pragma unroll
        for (int u = 0; u < CPT; u++) {
            int idx = tid + TPB * u;
            int s = idx >> 6, j = idx & 63;
            float ig = sig_hw(g_sm[s][j]);
            float fg = sig_hw(g_sm[s][H + j]);
            float gg = tanh_hw(g_sm[s][2 * H + j]);
            float og = sig_hw(g_sm[s][3 * H + j]);
            float c  = fg * c_reg[u] + ig * gg;
            c_reg[u] = c;
            h_sm[s][j] = og * tanh_hw(c);
        }
        __syncthreads();
    }

    // ---- head: pred = leaky_relu(h . Wd + bd, 0.2)
    int w = tid >> 5, lane = tid & 31;
    for (int s = w; s < BS; s += TPB / 32) {
        if (n0 + s < N) {
            float p = h_sm[s][lane] * Wd[lane] + h_sm[s][lane + 32] * Wd[lane + 32];
#pragma unroll
            for (int off = 16; off; off >>= 1) p += __shfl_down_sync(0xffffffffu, p, off);
            if (lane == 0) {
                p += bd[0];
                p = p > 0.f ? p : 0.2f * p;
                pred[n0 + s] = p;
            }
        }
    }
}

// Pairwise rank loss partials + masked MSE partials (deterministic, no atomics).
__global__ void pair_kernel(const float* __restrict__ pred, const float* __restrict__ ret,
                            const unsigned* __restrict__ mask, int N)
{
    __shared__ float p_sm[4096];
    __shared__ float t_sm[4096];
    __shared__ unsigned char m_sm[4096];
    __shared__ float red[256];
    const int tid = threadIdx.x;

    for (int n = tid; n < N; n += blockDim.x) {
        p_sm[n] = pred[n];
        t_sm[n] = ret[n];
        m_sm[n] = (mask[n] != 0u) ? 1 : 0;
    }
    __syncthreads();

    float rsum = 0.f;
    for (int i = blockIdx.x; i < N; i += gridDim.x) {
        if (!m_sm[i]) continue;
        float pi = p_sm[i], gi = t_sm[i];
        for (int jj = tid; jj < N; jj += blockDim.x) {
            float v = -(p_sm[jj] - pi) * (t_sm[jj] - gi);
            v = fmaxf(v, 0.f);
            rsum += v * (float)m_sm[jj];
        }
    }
    red[tid] = rsum;
    __syncthreads();
    for (int s = 128; s; s >>= 1) { if (tid < s) red[tid] += red[tid + s]; __syncthreads(); }
    if (tid == 0) g_rank_part[blockIdx.x] = red[0];

    if (blockIdx.x == 0) {
        float ssq = 0.f, sm = 0.f;
        for (int n = tid; n < N; n += blockDim.x) {
            float m = (float)m_sm[n];
            float d = p_sm[n] - t_sm[n];
            ssq += d * d * m;
            sm  += m;
        }
        __syncthreads();
        red[tid] = ssq; __syncthreads();
        for (int s = 128; s; s >>= 1) { if (tid < s) red[tid] += red[tid + s]; __syncthreads(); }
        if (tid == 0) g_reg_part[0] = red[0];
        __syncthreads();
        red[tid] = sm; __syncthreads();
        for (int s = 128; s; s >>= 1) { if (tid < s) red[tid] += red[tid + s]; __syncthreads(); }
        if (tid == 0) g_reg_part[1] = red[0];
    }
}

__global__ void finalize_kernel(float* __restrict__ out, int N)
{
    if (threadIdx.x == 0 && blockIdx.x == 0) {
        float srank = 0.f;
        for (int b = 0; b < RB; b++) srank += g_rank_part[b];
        float reg  = g_reg_part[0] / (g_reg_part[1] + 1e-8f);
        float rank = srank / ((float)N * (float)N);
        out[N]     = reg + rank;
        out[N + 1] = reg;
        out[N + 2] = rank;
    }
}

extern "C" void kernel_launch(void* const* d_in, const int* in_sizes, int n_in,
                              void* d_out, int out_size)
{
    const float*    feature = (const float*)d_in[0];
    const float*    ret     = (const float*)d_in[1];
    const unsigned* mask    = (const unsigned*)d_in[2];
    const float*    Wih     = (const float*)d_in[3];
    const float*    Whh     = (const float*)d_in[4];
    const float*    bih     = (const float*)d_in[5];
    const float*    bhh     = (const float*)d_in[6];
    const float*    Wd      = (const float*)d_in[7];
    const float*    bd      = (const float*)d_in[8];
    float* out = (float*)d_out;

    const int N = in_sizes[1];                 // 4096
    const int T = in_sizes[0] / (N * F);       // 512

    const int grid = (N + BS - 1) / BS;        // 147
    lstm_kernel<<<grid, TPB>>>(feature, Wih, Whh, bih, bhh, Wd, bd, out, N, T);
    pair_kernel<<<RB, 256>>>(out, ret, mask, N);
    finalize_kernel<<<1, 32>>>(out, N);
}

// round 10
// speedup vs baseline: 1.6580x; 1.0445x over previous
#include <cuda_runtime.h>

#define H    64
#define G    256
#define F    5
#define BS   28      // samples per block; grid=147 -> 1 CTA/SM, single wave
#define HS   14      // samples per thread-half
#define TPB  256
#define RB   128
#define CPT  (BS * H / TPB)   // 7 cells/thread in phase 2

typedef unsigned long long ull;

__device__ float g_rank_part[RB];
__device__ float g_reg_part[2];

__device__ __forceinline__ float tanh_hw(float x) {
    float y;
    asm("tanh.approx.f32 %0, %1;" : "=f"(y) : "f"(x));
    return y;
}
__device__ __forceinline__ float sig_hw(float x) {
    return fmaf(tanh_hw(0.5f * x), 0.5f, 0.5f);
}

// packed dual-FMA (sm_103a FFMA2), lanes = (even-k, odd-k) partials
__device__ __forceinline__ ull fma2(ull a, ull b, ull c) {
    ull d;
    asm("fma.rn.f32x2 %0, %1, %2, %3;" : "=l"(d) : "l"(a), "l"(b), "l"(c));
    return d;
}
__device__ __forceinline__ ull pack2(float lo, float hi) {
    return (ull)__float_as_uint(lo) | ((ull)__float_as_uint(hi) << 32);
}
__device__ __forceinline__ float f2lo(ull v) { return __uint_as_float((unsigned)v); }
__device__ __forceinline__ float f2hi(ull v) { return __uint_as_float((unsigned)(v >> 32)); }

__global__ __launch_bounds__(TPB, 1)
void lstm_kernel(const float* __restrict__ feature,
                 const float* __restrict__ Wih, const float* __restrict__ Whh,
                 const float* __restrict__ bih, const float* __restrict__ bhh,
                 const float* __restrict__ Wd,  const float* __restrict__ bd,
                 float* __restrict__ pred, int N, int T)
{
    const int tid  = threadIdx.x;
    const int half = tid >> 7;           // 0: samples 0..13, 1: samples 14..27
    const int rr   = tid & 127;
    const int r0   = 2 * rr, r1 = 2 * rr + 1;   // this thread's gate rows
    const int n0   = blockIdx.x * BS;
    const int sb   = half * HS;          // first sample of this half

    // Two Whh rows resident, k-packed f32x2 (128 regs)
    ull wa[H / 2], wb[H / 2];
    {
        const float4* pa = (const float4*)(Whh + r0 * H);
        const float4* pb = (const float4*)(Whh + r1 * H);
#pragma unroll
        for (int q = 0; q < H / 4; q++) {
            float4 va = pa[q], vb = pb[q];
            wa[2 * q]     = pack2(va.x, va.y);
            wa[2 * q + 1] = pack2(va.z, va.w);
            wb[2 * q]     = pack2(vb.x, vb.y);
            wb[2 * q + 1] = pack2(vb.z, vb.w);
        }
    }
    float wx0[F], wx1[F];
#pragma unroll
    for (int f = 0; f < F; f++) { wx0[f] = Wih[r0 * F + f]; wx1[f] = Wih[r1 * F + f]; }
    const float bias0 = bih[r0] + bhh[r0];
    const float bias1 = bih[r1] + bhh[r1];

    __shared__ __align__(16) float h_sm[BS][H];
    __shared__ float g_sm[BS][G];
    __shared__ __align__(16) float x_sm[2][BS][8];   // padded rows for float4

    float c_reg[CPT];
#pragma unroll
    for (int u = 0; u < CPT; u++) {
        c_reg[u] = 0.f;
        int idx = tid + TPB * u;
        h_sm[idx >> 6][idx & 63] = 0.f;
    }
    for (int i = tid; i < 2 * BS * 8; i += TPB) ((float*)x_sm)[i] = 0.f;
    __syncthreads();
    if (tid < BS * F) {
        int s = tid / F, f = tid % F;
        if (n0 + s < N) x_sm[0][s][f] = feature[(size_t)(n0 + s) * T * F + f];
    }
    __syncthreads();

    for (int t = 0; t < T; t++) {
        const int buf = t & 1;

        // ---- phase 1: two gate rows, this half's 14 samples
        // one LDS.128 of h feeds 4 FFMA2 (2 rows x 2 k)
#pragma unroll 2
        for (int i = 0; i < HS; i++) {
            const int s = sb + i;
            ull a0 = pack2(bias0, 0.f);
            ull a1 = pack2(bias1, 0.f);
            const ulonglong2* h2 = (const ulonglong2*)h_sm[s];   // uniform -> broadcast
#pragma unroll
            for (int q = 0; q < H / 4; q++) {
                ulonglong2 hv = h2[q];
                a0 = fma2(wa[2 * q],     hv.x, a0);
                a1 = fma2(wb[2 * q],     hv.x, a1);
                a0 = fma2(wa[2 * q + 1], hv.y, a0);
                a1 = fma2(wb[2 * q + 1], hv.y, a1);
            }
            float v0 = f2lo(a0) + f2hi(a0);
            float v1 = f2lo(a1) + f2hi(a1);
            const float4 xv = *(const float4*)x_sm[buf][s];
            const float  x4 = x_sm[buf][s][4];
            v0 = fmaf(wx0[0], xv.x, v0); v1 = fmaf(wx1[0], xv.x, v1);
            v0 = fmaf(wx0[1], xv.y, v0); v1 = fmaf(wx1[1], xv.y, v1);
            v0 = fmaf(wx0[2], xv.z, v0); v1 = fmaf(wx1[2], xv.z, v1);
            v0 = fmaf(wx0[3], xv.w, v0); v1 = fmaf(wx1[3], xv.w, v1);
            v0 = fmaf(wx0[4], x4,   v0); v1 = fmaf(wx1[4], x4,   v1);
            *(float2*)&g_sm[s][r0] = make_float2(v0, v1);        // STS.64
        }
        __syncthreads();

        // ---- prefetch x for t+1
        if (t + 1 < T && tid < BS * F) {
            int s = tid / F, f = tid % F;
            if (n0 + s < N)
                x_sm[buf ^ 1][s][f] =
                    feature[(size_t)(n0 + s) * T * F + (size_t)(t + 1) * F + f];
        }

        // ---- phase 2: LSTM cell update (gate order i,f,g,o), 7 cells/thread
#pragma unroll
        for (int u = 0; u < CPT; u++) {
            int idx = tid + TPB * u;
            int s = idx >> 6, j = idx & 63;
            float ig = sig_hw(g_sm[s][j]);
            float fg = sig_hw(g_sm[s][H + j]);
            float gg = tanh_hw(g_sm[s][2 * H + j]);
            float og = sig_hw(g_sm[s][3 * H + j]);
            float c  = fg * c_reg[u] + ig * gg;
            c_reg[u] = c;
            h_sm[s][j] = og * tanh_hw(c);
        }
        __syncthreads();
    }

    // ---- head: pred = leaky_relu(h . Wd + bd, 0.2)
    int w = tid >> 5, lane = tid & 31;
    for (int s = w; s < BS; s += TPB / 32) {
        if (n0 + s < N) {
            float p = h_sm[s][lane] * Wd[lane] + h_sm[s][lane + 32] * Wd[lane + 32];
#pragma unroll
            for (int off = 16; off; off >>= 1) p += __shfl_down_sync(0xffffffffu, p, off);
            if (lane == 0) {
                p += bd[0];
                p = p > 0.f ? p : 0.2f * p;
                pred[n0 + s] = p;
            }
        }
    }
}

// Pairwise rank loss partials + masked MSE partials (deterministic, no atomics).
__global__ void pair_kernel(const float* __restrict__ pred, const float* __restrict__ ret,
                            const unsigned* __restrict__ mask, int N)
{
    __shared__ float p_sm[4096];
    __shared__ float t_sm[4096];
    __shared__ unsigned char m_sm[4096];
    __shared__ float red[256];
    const int tid = threadIdx.x;

    for (int n = tid; n < N; n += blockDim.x) {
        p_sm[n] = pred[n];
        t_sm[n] = ret[n];
        m_sm[n] = (mask[n] != 0u) ? 1 : 0;
    }
    __syncthreads();

    float rsum = 0.f;
    for (int i = blockIdx.x; i < N; i += gridDim.x) {
        if (!m_sm[i]) continue;
        float pi = p_sm[i], gi = t_sm[i];
        for (int jj = tid; jj < N; jj += blockDim.x) {
            float v = -(p_sm[jj] - pi) * (t_sm[jj] - gi);
            v = fmaxf(v, 0.f);
            rsum += v * (float)m_sm[jj];
        }
    }
    red[tid] = rsum;
    __syncthreads();
    for (int s = 128; s; s >>= 1) { if (tid < s) red[tid] += red[tid + s]; __syncthreads(); }
    if (tid == 0) g_rank_part[blockIdx.x] = red[0];

    if (blockIdx.x == 0) {
        float ssq = 0.f, sm = 0.f;
        for (int n = tid; n < N; n += blockDim.x) {
            float m = (float)m_sm[n];
            float d = p_sm[n] - t_sm[n];
            ssq += d * d * m;
            sm  += m;
        }
        __syncthreads();
        red[tid] = ssq; __syncthreads();
        for (int s = 128; s; s >>= 1) { if (tid < s) red[tid] += red[tid + s]; __syncthreads(); }
        if (tid == 0) g_reg_part[0] = red[0];
        __syncthreads();
        red[tid] = sm; __syncthreads();
        for (int s = 128; s; s >>= 1) { if (tid < s) red[tid] += red[tid + s]; __syncthreads(); }
        if (tid == 0) g_reg_part[1] = red[0];
    }
}

__global__ void finalize_kernel(float* __restrict__ out, int N)
{
    if (threadIdx.x == 0 && blockIdx.x == 0) {
        float srank = 0.f;
        for (int b = 0; b < RB; b++) srank += g_rank_part[b];
        float reg  = g_reg_part[0] / (g_reg_part[1] + 1e-8f);
        float rank = srank / ((float)N * (float)N);
        out[N]     = reg + rank;
        out[N + 1] = reg;
        out[N + 2] = rank;
    }
}

extern "C" void kernel_launch(void* const* d_in, const int* in_sizes, int n_in,
                              void* d_out, int out_size)
{
    const float*    feature = (const float*)d_in[0];
    const float*    ret     = (const float*)d_in[1];
    const unsigned* mask    = (const unsigned*)d_in[2];
    const float*    Wih     = (const float*)d_in[3];
    const float*    Whh     = (const float*)d_in[4];
    const float*    bih     = (const float*)d_in[5];
    const float*    bhh     = (const float*)d_in[6];
    const float*    Wd      = (const float*)d_in[7];
    const float*    bd      = (const float*)d_in[8];
    float* out = (float*)d_out;

    const int N = in_sizes[1];                 // 4096
    const int T = in_sizes[0] / (N * F);       // 512

    const int grid = (N + BS - 1) / BS;        // 147
    lstm_kernel<<<grid, TPB>>>(feature, Wih, Whh, bih, bhh, Wd, bd, out, N, T);
    pair_kernel<<<RB, 256>>>(out, ret, mask, N);
    finalize_kernel<<<1, 32>>>(out, N);
}

// round 12
// speedup vs baseline: 1.7202x; 1.0375x over previous
#include <cuda_runtime.h>
#include <cstdint>

#define H    64
#define F    5
#define BS   28      // samples per block; grid=147 -> 1 CTA/SM, single wave
#define HS   14      // samples per half
#define TPB  256
#define RB   128

typedef unsigned long long ull;

// dynamic SMEM layout (floats):
//   h_sm  [28][64]           1792 f
//   x_sm  [2][28][8]          448 f
//   part  [2][2][14][64] f4 57344 B
#define SM_H    0
#define SM_X    (28 * 64)
#define SM_PART (28 * 64 + 2 * 28 * 8)                 // float4 region starts here
#define SMEM_BYTES ((28 * 64 + 2 * 28 * 8) * 4 + 2 * 2 * 14 * 64 * 16)

__device__ float g_rank_part[RB];
__device__ float g_reg_part[2];

__device__ __forceinline__ float tanh_hw(float x) {
    float y; asm("tanh.approx.f32 %0, %1;" : "=f"(y) : "f"(x)); return y;
}
__device__ __forceinline__ float sig_hw(float x) {
    return fmaf(tanh_hw(0.5f * x), 0.5f, 0.5f);
}
__device__ __forceinline__ ull fma2(ull a, ull b, ull c) {
    ull d;
    asm("fma.rn.f32x2 %0, %1, %2, %3;" : "=l"(d) : "l"(a), "l"(b), "l"(c));
    return d;
}
__device__ __forceinline__ ull pack2(float lo, float hi) {
    return (ull)__float_as_uint(lo) | ((ull)__float_as_uint(hi) << 32);
}
__device__ __forceinline__ float f2lo(ull v) { return __uint_as_float((unsigned)v); }
__device__ __forceinline__ float f2hi(ull v) { return __uint_as_float((unsigned)(v >> 32)); }

__global__ __launch_bounds__(TPB, 1)
void lstm_kernel(const float* __restrict__ feature,
                 const float* __restrict__ Wih, const float* __restrict__ Whh,
                 const float* __restrict__ bih, const float* __restrict__ bhh,
                 const float* __restrict__ Wd,  const float* __restrict__ bd,
                 float* __restrict__ pred, int N, int T)
{
    extern __shared__ float smem[];
    float*  h_sm = smem + SM_H;                  // [28][64]
    float*  x_sm = smem + SM_X;                  // [2][28][8]
    float4* part = (float4*)(smem + SM_PART);    // [half][kh][14][64]

    const int tid  = threadIdx.x;
    const int half = tid >> 7;                   // sample half: 0 -> 0..13, 1 -> 14..27
    const int idxh = tid & 127;
    const int u    = idxh & 63;                  // hidden unit
    const int kh   = idxh >> 6;                  // k-half: 0 -> k[0:32), 1 -> k[32:64)
    const int n0   = blockIdx.x * BS;
    const int sOff = half * HS;
    const int barid = half + 1;

    // 4 gate rows of unit u (i,f,g,o), my k-half only, k-packed f32x2: 64 ull
    ull wk[4][16];
#pragma unroll
    for (int g = 0; g < 4; g++) {
        const float4* wr = (const float4*)(Whh + (g * H + u) * H + kh * 32);
#pragma unroll
        for (int q = 0; q < 8; q++) {
            float4 v = wr[q];
            wk[g][2 * q]     = pack2(v.x, v.y);
            wk[g][2 * q + 1] = pack2(v.z, v.w);
        }
    }
    float wx[4][F], bb[4];
#pragma unroll
    for (int g = 0; g < 4; g++) {
        const int row = g * H + u;
#pragma unroll
        for (int f = 0; f < F; f++) wx[g][f] = Wih[row * F + f];
        bb[g] = bih[row] + bhh[row];
    }

    // init h=0, x buffers (per-half ownership not required pre-loop; full sync below)
    for (int i = tid; i < BS * H; i += TPB) h_sm[i] = 0.f;
    for (int i = tid; i < 2 * BS * 8; i += TPB) x_sm[i] = 0.f;
    __syncthreads();
    if (idxh < HS * F) {                         // per-half x(0) load
        int sl = idxh / F, f = idxh % F;
        int s = sOff + sl;
        if (n0 + s < N) x_sm[s * 8 + f] = feature[(size_t)(n0 + s) * T * F + f];
    }
    __syncthreads();

    float c_reg[7];
#pragma unroll
    for (int i = 0; i < 7; i++) c_reg[i] = 0.f;

    for (int t = 0; t < T; t++) {
        const int buf = t & 1;

        // ---- phase 1: partial gate dots for my 14 samples (4 chains, my k-half)
#pragma unroll 2
        for (int sl = 0; sl < HS; sl++) {
            const int s = sOff + sl;
            const ulonglong2* h2 = (const ulonglong2*)(h_sm + s * H + kh * 32);
            ull a0 = 0ULL, a1 = 0ULL, a2 = 0ULL, a3 = 0ULL;
#pragma unroll
            for (int q = 0; q < 8; q++) {
                ulonglong2 hv = h2[q];
                a0 = fma2(wk[0][2 * q], hv.x, a0);
                a1 = fma2(wk[1][2 * q], hv.x, a1);
                a2 = fma2(wk[2][2 * q], hv.x, a2);
                a3 = fma2(wk[3][2 * q], hv.x, a3);
                a0 = fma2(wk[0][2 * q + 1], hv.y, a0);
                a1 = fma2(wk[1][2 * q + 1], hv.y, a1);
                a2 = fma2(wk[2][2 * q + 1], hv.y, a2);
                a3 = fma2(wk[3][2 * q + 1], hv.y, a3);
            }
            float4 v = make_float4(f2lo(a0) + f2hi(a0), f2lo(a1) + f2hi(a1),
                                   f2lo(a2) + f2hi(a2), f2lo(a3) + f2hi(a3));
            if (kh == 0) {                       // bias + x-projection ride on k-half 0
                v.x += bb[0]; v.y += bb[1]; v.z += bb[2]; v.w += bb[3];
                const float* xs = x_sm + buf * BS * 8 + s * 8;
#pragma unroll
                for (int f = 0; f < F; f++) {
                    float xv = xs[f];
                    v.x = fmaf(wx[0][f], xv, v.x);
                    v.y = fmaf(wx[1][f], xv, v.y);
                    v.z = fmaf(wx[2][f], xv, v.z);
                    v.w = fmaf(wx[3][f], xv, v.w);
                }
            }
            part[((half * 2 + kh) * HS + sl) * H + u] = v;    // coalesced STS.128
        }
        asm volatile("bar.sync %0, 128;" :: "r"(barid) : "memory");

        // ---- prefetch x(t+1), per half
        if (t + 1 < T && idxh < HS * F) {
            int sl = idxh / F, f = idxh % F;
            int s = sOff + sl;
            if (n0 + s < N)
                x_sm[(buf ^ 1) * BS * 8 + s * 8 + f] =
                    feature[(size_t)(n0 + s) * T * F + (size_t)(t + 1) * F + f];
        }

        // ---- phase 2: cell update, 7 cells/thread within my half
#pragma unroll
        for (int i = 0; i < 7; i++) {
            const int cid = idxh + 128 * i;           // 0..895
            const int sl = cid >> 6, uu = cid & 63;
            float4 p0 = part[((half * 2 + 0) * HS + sl) * H + uu];
            float4 p1 = part[((half * 2 + 1) * HS + sl) * H + uu];
            float ig = sig_hw(p0.x + p1.x);
            float fg = sig_hw(p0.y + p1.y);
            float gg = tanh_hw(p0.z + p1.z);
            float og = sig_hw(p0.w + p1.w);
            float c  = fg * c_reg[i] + ig * gg;
            c_reg[i] = c;
            h_sm[(sOff + sl) * H + uu] = og * tanh_hw(c);
        }
        asm volatile("bar.sync %0, 128;" :: "r"(barid) : "memory");
    }

    // ---- head: pred = leaky_relu(h . Wd + bd, 0.2); my half's samples
    int w = idxh >> 5, lane = idxh & 31;
    for (int sl = w; sl < HS; sl += 4) {
        const int s = sOff + sl;
        if (n0 + s < N) {
            float p = h_sm[s * H + lane] * Wd[lane]
                    + h_sm[s * H + lane + 32] * Wd[lane + 32];
#pragma unroll
            for (int off = 16; off; off >>= 1) p += __shfl_down_sync(0xffffffffu, p, off);
            if (lane == 0) {
                p += bd[0];
                p = p > 0.f ? p : 0.2f * p;
                pred[n0 + s] = p;
            }
        }
    }
}

// Pairwise rank loss partials + masked MSE partials (deterministic, no atomics).
__global__ void pair_kernel(const float* __restrict__ pred, const float* __restrict__ ret,
                            const unsigned* __restrict__ mask, int N)
{
    __shared__ float p_sm[4096];
    __shared__ float t_sm[4096];
    __shared__ unsigned char m_sm[4096];
    __shared__ float red[256];
    const int tid = threadIdx.x;

    for (int n = tid; n < N; n += blockDim.x) {
        p_sm[n] = pred[n];
        t_sm[n] = ret[n];
        m_sm[n] = (mask[n] != 0u) ? 1 : 0;
    }
    __syncthreads();

    float rsum = 0.f;
    for (int i = blockIdx.x; i < N; i += gridDim.x) {
        if (!m_sm[i]) continue;
        float pi = p_sm[i], gi = t_sm[i];
        for (int j = tid; j < N; j += blockDim.x) {
            float v = -(p_sm[j] - pi) * (t_sm[j] - gi);
            v = fmaxf(v, 0.f);
            rsum += v * (float)m_sm[j];
        }
    }
    red[tid] = rsum;
    __syncthreads();
    for (int s = 128; s; s >>= 1) { if (tid < s) red[tid] += red[tid + s]; __syncthreads(); }
    if (tid == 0) g_rank_part[blockIdx.x] = red[0];

    if (blockIdx.x == 0) {
        float ssq = 0.f, sm = 0.f;
        for (int n = tid; n < N; n += blockDim.x) {
            float m = (float)m_sm[n];
            float d = p_sm[n] - t_sm[n];
            ssq += d * d * m;
            sm  += m;
        }
        __syncthreads();
        red[tid] = ssq; __syncthreads();
        for (int s = 128; s; s >>= 1) { if (tid < s) red[tid] += red[tid + s]; __syncthreads(); }
        if (tid == 0) g_reg_part[0] = red[0];
        __syncthreads();
        red[tid] = sm; __syncthreads();
        for (int s = 128; s; s >>= 1) { if (tid < s) red[tid] += red[tid + s]; __syncthreads(); }
        if (tid == 0) g_reg_part[1] = red[0];
    }
}

__global__ void finalize_kernel(float* __restrict__ out, int N)
{
    if (threadIdx.x == 0 && blockIdx.x == 0) {
        float srank = 0.f;
        for (int b = 0; b < RB; b++) srank += g_rank_part[b];
        float reg  = g_reg_part[0] / (g_reg_part[1] + 1e-8f);
        float rank = srank / ((float)N * (float)N);
        out[N]     = reg + rank;
        out[N + 1] = reg;
        out[N + 2] = rank;
    }
}

extern "C" void kernel_launch(void* const* d_in, const int* in_sizes, int n_in,
                              void* d_out, int out_size)
{
    const float*    feature = (const float*)d_in[0];
    const float*    ret     = (const float*)d_in[1];
    const unsigned* mask    = (const unsigned*)d_in[2];
    const float*    Wih     = (const float*)d_in[3];
    const float*    Whh     = (const float*)d_in[4];
    const float*    bih     = (const float*)d_in[5];
    const float*    bhh     = (const float*)d_in[6];
    const float*    Wd      = (const float*)d_in[7];
    const float*    bd      = (const float*)d_in[8];
    float* out = (float*)d_out;

    const int N = in_sizes[1];                 // 4096
    const int T = in_sizes[0] / (N * F);       // 512

    cudaFuncSetAttribute(lstm_kernel, cudaFuncAttributeMaxDynamicSharedMemorySize, SMEM_BYTES);

    const int grid = (N + BS - 1) / BS;        // 147
    lstm_kernel<<<grid, TPB, SMEM_BYTES>>>(feature, Wih, Whh, bih, bhh, Wd, bd, out, N, T);
    pair_kernel<<<RB, 256>>>(out, ret, mask, N);
    finalize_kernel<<<1, 32>>>(out, N);
}

// round 13
// speedup vs baseline: 1.8678x; 1.0858x over previous
#include <cuda_runtime.h>
#include <cstdint>

#define H    64
#define F    5
#define BS   28      // samples per block; grid=147 -> 1 CTA/SM, single wave
#define HS   14      // samples per half
#define TPB  256
#define RB   128
#define HSTR 68      // h row stride in floats: 32 | 4 pad | 32  (bank-disjoint halves)

typedef unsigned long long ull;

__device__ float g_rank_part[RB];
__device__ float g_reg_part[2];

__device__ __forceinline__ float tanh_hw(float x) {
    float y; asm("tanh.approx.f32 %0, %1;" : "=f"(y) : "f"(x)); return y;
}
__device__ __forceinline__ float sig_hw(float x) {
    return fmaf(tanh_hw(0.5f * x), 0.5f, 0.5f);
}
__device__ __forceinline__ ull fma2(ull a, ull b, ull c) {
    ull d;
    asm("fma.rn.f32x2 %0, %1, %2, %3;" : "=l"(d) : "l"(a), "l"(b), "l"(c));
    return d;
}
__device__ __forceinline__ ull pack2(float lo, float hi) {
    return (ull)__float_as_uint(lo) | ((ull)__float_as_uint(hi) << 32);
}
__device__ __forceinline__ float f2lo(ull v) { return __uint_as_float((unsigned)v); }
__device__ __forceinline__ float f2hi(ull v) { return __uint_as_float((unsigned)(v >> 32)); }

__global__ __launch_bounds__(TPB, 1)
void lstm_kernel(const float* __restrict__ feature,
                 const float* __restrict__ Wih, const float* __restrict__ Whh,
                 const float* __restrict__ bih, const float* __restrict__ bhh,
                 const float* __restrict__ Wd,  const float* __restrict__ bd,
                 float* __restrict__ pred, int N, int T)
{
    const int tid   = threadIdx.x;
    const int half  = tid >> 7;                 // sample half: 0 -> 0..13, 1 -> 14..27
    const int idxh  = tid & 127;
    const int lane  = tid & 31;
    const int kh    = lane >> 4;                // k-half is a LANE bit -> shfl partner
    const int u     = ((idxh >> 5) << 4) + (lane & 15);   // hidden unit 0..63
    const int n0    = blockIdx.x * BS;
    const int sOff  = half * HS;
    const int barid = half + 1;

    // 4 gate rows of unit u (i,f,g,o), my k-half, k-packed f32x2: 64 ull
    ull wk[4][16];
#pragma unroll
    for (int g = 0; g < 4; g++) {
        const float4* wr = (const float4*)(Whh + (g * H + u) * H + kh * 32);
#pragma unroll
        for (int q = 0; q < 8; q++) {
            float4 v = wr[q];
            wk[g][2 * q]     = pack2(v.x, v.y);
            wk[g][2 * q + 1] = pack2(v.z, v.w);
        }
    }
    float wx[4][F], bb[4];
#pragma unroll
    for (int g = 0; g < 4; g++) {
        const int row = g * H + u;
#pragma unroll
        for (int f = 0; f < F; f++) wx[g][f] = Wih[row * F + f];
        bb[g] = bih[row] + bhh[row];
    }

    __shared__ __align__(16) float hbuf[BS][HSTR];   // [s][k<32 at k, k>=32 at 36+k-32]
    __shared__ float x_sm[2][BS][8];

    for (int i = tid; i < BS * HSTR; i += TPB) ((float*)hbuf)[i] = 0.f;
    for (int i = tid; i < 2 * BS * 8; i += TPB) ((float*)x_sm)[i] = 0.f;
    __syncthreads();
    if (idxh < HS * F) {
        int sl = idxh / F, f = idxh % F;
        int s = sOff + sl;
        if (n0 + s < N) x_sm[0][s][f] = feature[(size_t)(n0 + s) * T * F + f];
    }
    __syncthreads();

    const int uoff = u + ((u >> 5) << 2);       // h write word offset within row
    float c_reg[7];
#pragma unroll
    for (int i = 0; i < 7; i++) c_reg[i] = 0.f;

    for (int t = 0; t < T; t++) {
        const int buf = t & 1;
        float4 garr[7];                          // my 7 cells' combined gate preacts

        // ---- phase 1: partial dots (my k-half) + bfly combine; stage owned cells
#pragma unroll
        for (int sl = 0; sl < HS; sl++) {
            const int s = sOff + sl;
            const ulonglong2* h2 = (const ulonglong2*)(&hbuf[s][kh * 36]);
            ull a0 = 0ULL, a1 = 0ULL, a2 = 0ULL, a3 = 0ULL;
#pragma unroll
            for (int q = 0; q < 4; q++) {
                ulonglong2 hv0 = h2[2 * q];
                ulonglong2 hv1 = h2[2 * q + 1];
                a0 = fma2(wk[0][4 * q], hv0.x, a0);
                a1 = fma2(wk[1][4 * q], hv0.x, a1);
                a2 = fma2(wk[2][4 * q], hv0.x, a2);
                a3 = fma2(wk[3][4 * q], hv0.x, a3);
                a0 = fma2(wk[0][4 * q + 1], hv0.y, a0);
                a1 = fma2(wk[1][4 * q + 1], hv0.y, a1);
                a2 = fma2(wk[2][4 * q + 1], hv0.y, a2);
                a3 = fma2(wk[3][4 * q + 1], hv0.y, a3);
                a0 = fma2(wk[0][4 * q + 2], hv1.x, a0);
                a1 = fma2(wk[1][4 * q + 2], hv1.x, a1);
                a2 = fma2(wk[2][4 * q + 2], hv1.x, a2);
                a3 = fma2(wk[3][4 * q + 2], hv1.x, a3);
                a0 = fma2(wk[0][4 * q + 3], hv1.y, a0);
                a1 = fma2(wk[1][4 * q + 3], hv1.y, a1);
                a2 = fma2(wk[2][4 * q + 3], hv1.y, a2);
                a3 = fma2(wk[3][4 * q + 3], hv1.y, a3);
            }
            float4 v = make_float4(f2lo(a0) + f2hi(a0), f2lo(a1) + f2hi(a1),
                                   f2lo(a2) + f2hi(a2), f2lo(a3) + f2hi(a3));
            if (kh == 0) {                       // bias + x ride on k-half 0
                v.x += bb[0]; v.y += bb[1]; v.z += bb[2]; v.w += bb[3];
                const float* xs = x_sm[buf][s];
#pragma unroll
                for (int f = 0; f < F; f++) {
                    float xv = xs[f];
                    v.x = fmaf(wx[0][f], xv, v.x);
                    v.y = fmaf(wx[1][f], xv, v.y);
                    v.z = fmaf(wx[2][f], xv, v.z);
                    v.w = fmaf(wx[3][f], xv, v.w);
                }
            }
            // combine k-halves in registers (partner is lane ^ 16)
            float4 p;
            p.x = __shfl_xor_sync(0xffffffffu, v.x, 16);
            p.y = __shfl_xor_sync(0xffffffffu, v.y, 16);
            p.z = __shfl_xor_sync(0xffffffffu, v.z, 16);
            p.w = __shfl_xor_sync(0xffffffffu, v.w, 16);
            // ownership: kh=0 -> sl 0..6, kh=1 -> sl 7..13
            const bool own = (kh == 0) ? (sl < 7) : (sl >= 7);
            const int  gi  = (sl < 7) ? sl : (sl - 7);
            if (own)
                garr[gi] = make_float4(v.x + p.x, v.y + p.y, v.z + p.z, v.w + p.w);
        }

        // ---- prefetch x(t+1), per half
        if (t + 1 < T && idxh < HS * F) {
            int sl = idxh / F, f = idxh % F;
            int s = sOff + sl;
            if (n0 + s < N)
                x_sm[buf ^ 1][s][f] =
                    feature[(size_t)(n0 + s) * T * F + (size_t)(t + 1) * F + f];
        }

        // ---- phase 2: cell updates for my 7 cells (no divergence)
        const int sBase = sOff + kh * 7;
#pragma unroll
        for (int i = 0; i < 7; i++) {
            float4 gv = garr[i];
            float ig = sig_hw(gv.x);
            float fg = sig_hw(gv.y);
            float gg = tanh_hw(gv.z);
            float og = sig_hw(gv.w);
            float c  = fg * c_reg[i] + ig * gg;
            c_reg[i] = c;
            hbuf[sBase + i][uoff] = og * tanh_hw(c);
        }
        asm volatile("bar.sync %0, 128;" :: "r"(barid) : "memory");
    }

    // ---- head: pred = leaky_relu(h . Wd + bd, 0.2); my half's samples
    int w4 = idxh >> 5;
    for (int sl = w4; sl < HS; sl += 4) {
        const int s = sOff + sl;
        if (n0 + s < N) {
            float p = hbuf[s][lane] * Wd[lane] + hbuf[s][36 + lane] * Wd[lane + 32];
#pragma unroll
            for (int off = 16; off; off >>= 1) p += __shfl_down_sync(0xffffffffu, p, off);
            if (lane == 0) {
                p += bd[0];
                p = p > 0.f ? p : 0.2f * p;
                pred[n0 + s] = p;
            }
        }
    }
}

// Pairwise rank loss partials + masked MSE partials (deterministic, no atomics).
__global__ void pair_kernel(const float* __restrict__ pred, const float* __restrict__ ret,
                            const unsigned* __restrict__ mask, int N)
{
    __shared__ float p_sm[4096];
    __shared__ float t_sm[4096];
    __shared__ unsigned char m_sm[4096];
    __shared__ float red[256];
    const int tid = threadIdx.x;

    for (int n = tid; n < N; n += blockDim.x) {
        p_sm[n] = pred[n];
        t_sm[n] = ret[n];
        m_sm[n] = (mask[n] != 0u) ? 1 : 0;
    }
    __syncthreads();

    float rsum = 0.f;
    for (int i = blockIdx.x; i < N; i += gridDim.x) {
        if (!m_sm[i]) continue;
        float pi = p_sm[i], gi = t_sm[i];
        for (int j = tid; j < N; j += blockDim.x) {
            float v = -(p_sm[j] - pi) * (t_sm[j] - gi);
            v = fmaxf(v, 0.f);
            rsum += v * (float)m_sm[j];
        }
    }
    red[tid] = rsum;
    __syncthreads();
    for (int s = 128; s; s >>= 1) { if (tid < s) red[tid] += red[tid + s]; __syncthreads(); }
    if (tid == 0) g_rank_part[blockIdx.x] = red[0];

    if (blockIdx.x == 0) {
        float ssq = 0.f, sm = 0.f;
        for (int n = tid; n < N; n += blockDim.x) {
            float m = (float)m_sm[n];
            float d = p_sm[n] - t_sm[n];
            ssq += d * d * m;
            sm  += m;
        }
        __syncthreads();
        red[tid] = ssq; __syncthreads();
        for (int s = 128; s; s >>= 1) { if (tid < s) red[tid] += red[tid + s]; __syncthreads(); }
        if (tid == 0) g_reg_part[0] = red[0];
        __syncthreads();
        red[tid] = sm; __syncthreads();
        for (int s = 128; s; s >>= 1) { if (tid < s) red[tid] += red[tid + s]; __syncthreads(); }
        if (tid == 0) g_reg_part[1] = red[0];
    }
}

__global__ void finalize_kernel(float* __restrict__ out, int N)
{
    if (threadIdx.x == 0 && blockIdx.x == 0) {
        float srank = 0.f;
        for (int b = 0; b < RB; b++) srank += g_rank_part[b];
        float reg  = g_reg_part[0] / (g_reg_part[1] + 1e-8f);
        float rank = srank / ((float)N * (float)N);
        out[N]     = reg + rank;
        out[N + 1] = reg;
        out[N + 2] = rank;
    }
}

extern "C" void kernel_launch(void* const* d_in, const int* in_sizes, int n_in,
                              void* d_out, int out_size)
{
    const float*    feature = (const float*)d_in[0];
    const float*    ret     = (const float*)d_in[1];
    const unsigned* mask    = (const unsigned*)d_in[2];
    const float*    Wih     = (const float*)d_in[3];
    const float*    Whh     = (const float*)d_in[4];
    const float*    bih     = (const float*)d_in[5];
    const float*    bhh     = (const float*)d_in[6];
    const float*    Wd      = (const float*)d_in[7];
    const float*    bd      = (const float*)d_in[8];
    float* out = (float*)d_out;

    const int N = in_sizes[1];                 // 4096
    const int T = in_sizes[0] / (N * F);       // 512

    const int grid = (N + BS - 1) / BS;        // 147
    lstm_kernel<<<grid, TPB>>>(feature, Wih, Whh, bih, bhh, Wd, bd, out, N, T);
    pair_kernel<<<RB, 256>>>(out, ret, mask, N);
    finalize_kernel<<<1, 32>>>(out, N);
}

// round 14
// speedup vs baseline: 2.3050x; 1.2341x over previous
#include <cuda_runtime.h>
#include <cstdint>

#define H     64
#define F     5
#define BS    32     // samples per CTA; grid = 4096/32 = 128, single wave
#define TPB   256
#define RB    128
#define DST   36     // D buffer row stride (floats)

// dynamic SMEM byte offsets (all 16B aligned)
#define BHI_B  0        // B hi frags: 8 kc * 264 u32 (256 + 8 pad)
#define BLO_B  8448
#define BXH_B  16896    // ext B frags (x hi + ones): 264 u32
#define BXL_B  17952
#define DBUF_B 19008    // D: 256 x 36 f32
#define SMEMB  55872

__device__ float g_rank_part[RB];
__device__ float g_reg_part[2];

__device__ __forceinline__ float tanh_hw(float x) {
    float y; asm("tanh.approx.f32 %0, %1;" : "=f"(y) : "f"(x)); return y;
}
__device__ __forceinline__ float sig_hw(float x) {
    return fmaf(tanh_hw(0.5f * x), 0.5f, 0.5f);
}
__device__ __forceinline__ uint32_t tf32u(float x) {
    uint32_t u; asm("cvt.rna.tf32.f32 %0, %1;" : "=r"(u) : "f"(x)); return u;
}
__device__ __forceinline__ void mma8(float* c, const uint32_t* a, const uint32_t* b) {
    asm volatile("mma.sync.aligned.m16n8k8.row.col.f32.tf32.tf32.f32 "
        "{%0,%1,%2,%3}, {%4,%5,%6,%7}, {%8,%9}, {%0,%1,%2,%3};"
        : "+f"(c[0]), "+f"(c[1]), "+f"(c[2]), "+f"(c[3])
        : "r"(a[0]), "r"(a[1]), "r"(a[2]), "r"(a[3]), "r"(b[0]), "r"(b[1]));
}

__global__ __launch_bounds__(TPB, 1)
void lstm_kernel(const float* __restrict__ feature,
                 const float* __restrict__ Wih, const float* __restrict__ Whh,
                 const float* __restrict__ bih, const float* __restrict__ bhh,
                 const float* __restrict__ Wd,  const float* __restrict__ bd,
                 float* __restrict__ pred, int N, int T)
{
    extern __shared__ char smc[];
    uint32_t* smw  = (uint32_t*)smc;
    float*    dbuf = (float*)(smc + DBUF_B);

    const int tid = threadIdx.x, w = tid >> 5, lane = tid & 31;
    const int g   = lane >> 2,  tq = lane & 3;
    const int n0  = blockIdx.x * BS;

    // ---- preload A fragments: Whh 3xTF32 split + ext (Wih/bias) ----
    uint32_t aHi[2][8][4], aLo[2][8][4], AE1[2][4], AE2[2][4];
#pragma unroll
    for (int mt = 0; mt < 2; mt++) {
        const int r0 = 32 * w + 16 * mt + g, r1 = r0 + 8;
#pragma unroll
        for (int kc = 0; kc < 8; kc++) {
            const int k0 = 8 * kc + tq, k1 = k0 + 4;
            float v0 = Whh[r0 * H + k0], v1 = Whh[r1 * H + k0];
            float v2 = Whh[r0 * H + k1], v3 = Whh[r1 * H + k1];
            uint32_t h0 = tf32u(v0), h1 = tf32u(v1), h2 = tf32u(v2), h3 = tf32u(v3);
            aHi[mt][kc][0] = h0; aHi[mt][kc][1] = h1; aHi[mt][kc][2] = h2; aHi[mt][kc][3] = h3;
            aLo[mt][kc][0] = tf32u(v0 - __uint_as_float(h0));
            aLo[mt][kc][1] = tf32u(v1 - __uint_as_float(h1));
            aLo[mt][kc][2] = tf32u(v2 - __uint_as_float(h2));
            aLo[mt][kc][3] = tf32u(v3 - __uint_as_float(h3));
        }
        // ext chunk cols: 0-4 = Wih, 5 = bias, 6-7 = 0
        float e0 = Wih[r0 * F + tq], e1 = Wih[r1 * F + tq];
        float e2 = 0.f, e3 = 0.f;
        if (tq == 0)      { e2 = Wih[r0 * F + 4];     e3 = Wih[r1 * F + 4]; }
        else if (tq == 1) { e2 = bih[r0] + bhh[r0];   e3 = bih[r1] + bhh[r1]; }
        uint32_t q0 = tf32u(e0), q1 = tf32u(e1), q2 = tf32u(e2), q3 = tf32u(e3);
        AE1[mt][0] = q0; AE1[mt][1] = q1; AE1[mt][2] = q2; AE1[mt][3] = q3;
        AE2[mt][0] = tf32u(e0 - __uint_as_float(q0));
        AE2[mt][1] = tf32u(e1 - __uint_as_float(q1));
        AE2[mt][2] = tf32u(e2 - __uint_as_float(q2));
        AE2[mt][3] = tf32u(e3 - __uint_as_float(q3));
    }

    // x staging role
    const int  sx  = tid / 5, fx = tid - 5 * sx;
    const bool isx = tid < BS * F;
    uint32_t bxH = 0, bxL = 0;
    if (isx) {
        uint32_t off = (((sx >> 3) * 32 + (sx & 7) * 4 + (fx & 3)) * 2 + (fx >> 2));
        bxH = (BXH_B >> 2) + off; bxL = (BXL_B >> 2) + off;
    }

    // zero B-fragment region (h(0) = 0)
    for (int i = tid; i < DBUF_B / 4; i += TPB) smw[i] = 0;
    __syncthreads();
    if (tid < 32) {   // constant-1 column (k=5 of ext hi) for bias
        int nt = tid >> 3, gg = tid & 7;
        smw[(BXH_B >> 2) + ((nt * 32 + 4 * gg + 1) * 2 + 1)] = __float_as_uint(1.0f);
    }
    if (isx && n0 + sx < N) {   // x(0)
        float xv = feature[(size_t)(n0 + sx) * T * F + fx];
        uint32_t hi = tf32u(xv);
        smw[bxH] = hi;
        smw[bxL] = tf32u(xv - __uint_as_float(hi));
    }
    __syncthreads();

    // cell role: unit u, samples s0..s0+7
    const int u = tid & 63, sg = tid >> 6, s0 = 8 * sg;
    const uint32_t scH = (BHI_B >> 2) + (u >> 3) * 264 + (sg * 32 + (u & 3)) * 2 + ((u & 7) >> 2);
    const uint32_t scL = scH + (BLO_B - BHI_B) / 4;
    float c_reg[8];
#pragma unroll
    for (int i = 0; i < 8; i++) c_reg[i] = 0.f;

    const uint2* pBH = (const uint2*)(smc + BHI_B);
    const uint2* pBL = (const uint2*)(smc + BLO_B);
    const uint2* pXH = (const uint2*)(smc + BXH_B);
    const uint2* pXL = (const uint2*)(smc + BXL_B);

    for (int t = 0; t < T; t++) {
        // prefetch x(t+1)
        float xv = 0.f;
        const bool xok = isx && (t + 1 < T) && (n0 + sx < N);
        if (xok) xv = feature[(size_t)(n0 + sx) * T * F + (size_t)(t + 1) * F + fx];

        float C[2][4][4];
#pragma unroll
        for (int mt = 0; mt < 2; mt++)
#pragma unroll
            for (int nt = 0; nt < 4; nt++)
#pragma unroll
                for (int q = 0; q < 4; q++) C[mt][nt][q] = 0.f;

        // ---- 3xTF32 mainloop over K ----
#pragma unroll
        for (int kc = 0; kc < 8; kc++) {
            uint2 bh[4], bl[4];
#pragma unroll
            for (int nt = 0; nt < 4; nt++) bh[nt] = pBH[kc * 132 + nt * 32 + lane];
#pragma unroll
            for (int mt = 0; mt < 2; mt++)
#pragma unroll
                for (int nt = 0; nt < 4; nt++)
                    mma8(C[mt][nt], aHi[mt][kc], (const uint32_t*)&bh[nt]);
#pragma unroll
            for (int nt = 0; nt < 4; nt++) bl[nt] = pBL[kc * 132 + nt * 32 + lane];
#pragma unroll
            for (int mt = 0; mt < 2; mt++)
#pragma unroll
                for (int nt = 0; nt < 4; nt++)
                    mma8(C[mt][nt], aLo[mt][kc], (const uint32_t*)&bh[nt]);
#pragma unroll
            for (int mt = 0; mt < 2; mt++)
#pragma unroll
                for (int nt = 0; nt < 4; nt++)
                    mma8(C[mt][nt], aHi[mt][kc], (const uint32_t*)&bl[nt]);
        }
        // ---- ext chunks: Wih·x + bias ----
        {
            uint2 xh[4], xl[4];
#pragma unroll
            for (int nt = 0; nt < 4; nt++) { xh[nt] = pXH[nt * 32 + lane]; xl[nt] = pXL[nt * 32 + lane]; }
#pragma unroll
            for (int mt = 0; mt < 2; mt++)
#pragma unroll
                for (int nt = 0; nt < 4; nt++) {
                    mma8(C[mt][nt], AE1[mt], (const uint32_t*)&xh[nt]);
                    mma8(C[mt][nt], AE2[mt], (const uint32_t*)&xh[nt]);
                    mma8(C[mt][nt], AE1[mt], (const uint32_t*)&xl[nt]);
                }
        }

        // ---- store D fragments ----
#pragma unroll
        for (int mt = 0; mt < 2; mt++) {
            const int r0 = 32 * w + 16 * mt + g;
#pragma unroll
            for (int nt = 0; nt < 4; nt++) {
                float* p = dbuf + r0 * DST + 8 * nt + 2 * tq;
                *(float2*)p = make_float2(C[mt][nt][0], C[mt][nt][1]);
                *(float2*)(p + 8 * DST) = make_float2(C[mt][nt][2], C[mt][nt][3]);
            }
        }
        __syncthreads();

        // ---- epilogue: gates -> cell update -> h split back into B frags ----
        float ga[4][8];
#pragma unroll
        for (int g4 = 0; g4 < 4; g4++) {
            const float* row = dbuf + (g4 * 64 + u) * DST + s0;
            float4 qa = *(const float4*)row;
            float4 qb = *(const float4*)(row + 4);
            ga[g4][0] = qa.x; ga[g4][1] = qa.y; ga[g4][2] = qa.z; ga[g4][3] = qa.w;
            ga[g4][4] = qb.x; ga[g4][5] = qb.y; ga[g4][6] = qb.z; ga[g4][7] = qb.w;
        }
        if (t < T - 1) {
#pragma unroll
            for (int i = 0; i < 8; i++) {
                float ig = sig_hw(ga[0][i]);
                float fg = sig_hw(ga[1][i]);
                float gg = tanh_hw(ga[2][i]);
                float og = sig_hw(ga[3][i]);
                float c  = fg * c_reg[i] + ig * gg;
                c_reg[i] = c;
                float hv = og * tanh_hw(c);
                uint32_t hb = tf32u(hv);
                smw[scH + i * 8] = hb;
                smw[scL + i * 8] = tf32u(hv - __uint_as_float(hb));
            }
        } else {
#pragma unroll
            for (int i = 0; i < 8; i++) {
                float ig = sig_hw(ga[0][i]);
                float fg = sig_hw(ga[1][i]);
                float gg = tanh_hw(ga[2][i]);
                float og = sig_hw(ga[3][i]);
                float c  = fg * c_reg[i] + ig * gg;
                dbuf[u * DST + s0 + i] = og * tanh_hw(c);   // own slots only: race-free
            }
        }
        if (xok) {
            uint32_t hb = tf32u(xv);
            smw[bxH] = hb;
            smw[bxL] = tf32u(xv - __uint_as_float(hb));
        }
        __syncthreads();
    }

    // ---- head: pred = leaky_relu(h . Wd + bd, 0.2); warp w -> samples 4w..4w+3
#pragma unroll
    for (int sl = 0; sl < 4; sl++) {
        const int s = 4 * w + sl;
        float p = dbuf[lane * DST + s] * Wd[lane]
                + dbuf[(lane + 32) * DST + s] * Wd[lane + 32];
#pragma unroll
        for (int off = 16; off; off >>= 1) p += __shfl_down_sync(0xffffffffu, p, off);
        if (lane == 0 && n0 + s < N) {
            p += bd[0];
            p = p > 0.f ? p : 0.2f * p;
            pred[n0 + s] = p;
        }
    }
}

// Pairwise rank loss partials + masked MSE partials (deterministic, no atomics).
__global__ void pair_kernel(const float* __restrict__ pred, const float* __restrict__ ret,
                            const unsigned* __restrict__ mask, int N)
{
    __shared__ float p_sm[4096];
    __shared__ float t_sm[4096];
    __shared__ unsigned char m_sm[4096];
    __shared__ float red[256];
    const int tid = threadIdx.x;

    for (int n = tid; n < N; n += blockDim.x) {
        p_sm[n] = pred[n];
        t_sm[n] = ret[n];
        m_sm[n] = (mask[n] != 0u) ? 1 : 0;
    }
    __syncthreads();

    float rsum = 0.f;
    for (int i = blockIdx.x; i < N; i += gridDim.x) {
        if (!m_sm[i]) continue;
        float pi = p_sm[i], gi = t_sm[i];
        for (int j = tid; j < N; j += blockDim.x) {
            float v = -(p_sm[j] - pi) * (t_sm[j] - gi);
            v = fmaxf(v, 0.f);
            rsum += v * (float)m_sm[j];
        }
    }
    red[tid] = rsum;
    __syncthreads();
    for (int s = 128; s; s >>= 1) { if (tid < s) red[tid] += red[tid + s]; __syncthreads(); }
    if (tid == 0) g_rank_part[blockIdx.x] = red[0];

    if (blockIdx.x == 0) {
        float ssq = 0.f, sm = 0.f;
        for (int n = tid; n < N; n += blockDim.x) {
            float m = (float)m_sm[n];
            float d = p_sm[n] - t_sm[n];
            ssq += d * d * m;
            sm  += m;
        }
        __syncthreads();
        red[tid] = ssq; __syncthreads();
        for (int s = 128; s; s >>= 1) { if (tid < s) red[tid] += red[tid + s]; __syncthreads(); }
        if (tid == 0) g_reg_part[0] = red[0];
        __syncthreads();
        red[tid] = sm; __syncthreads();
        for (int s = 128; s; s >>= 1) { if (tid < s) red[tid] += red[tid + s]; __syncthreads(); }
        if (tid == 0) g_reg_part[1] = red[0];
    }
}

__global__ void finalize_kernel(float* __restrict__ out, int N)
{
    if (threadIdx.x == 0 && blockIdx.x == 0) {
        float srank = 0.f;
        for (int b = 0; b < RB; b++) srank += g_rank_part[b];
        float reg  = g_reg_part[0] / (g_reg_part[1] + 1e-8f);
        float rank = srank / ((float)N * (float)N);
        out[N]     = reg + rank;
        out[N + 1] = reg;
        out[N + 2] = rank;
    }
}

extern "C" void kernel_launch(void* const* d_in, const int* in_sizes, int n_in,
                              void* d_out, int out_size)
{
    const float*    feature = (const float*)d_in[0];
    const float*    ret     = (const float*)d_in[1];
    const unsigned* mask    = (const unsigned*)d_in[2];
    const float*    Wih     = (const float*)d_in[3];
    const float*    Whh     = (const float*)d_in[4];
    const float*    bih     = (const float*)d_in[5];
    const float*    bhh     = (const float*)d_in[6];
    const float*    Wd      = (const float*)d_in[7];
    const float*    bd      = (const float*)d_in[8];
    float* out = (float*)d_out;

    const int N = in_sizes[1];                 // 4096
    const int T = in_sizes[0] / (N * F);       // 512

    cudaFuncSetAttribute(lstm_kernel, cudaFuncAttributeMaxDynamicSharedMemorySize, SMEMB);

    const int grid = (N + BS - 1) / BS;        // 128
    lstm_kernel<<<grid, TPB, SMEMB>>>(feature, Wih, Whh, bih, bhh, Wd, bd, out, N, T);
    pair_kernel<<<RB, 256>>>(out, ret, mask, N);
    finalize_kernel<<<1, 32>>>(out, N);
}

// round 15
// speedup vs baseline: 2.6477x; 1.1487x over previous
#include <cuda_runtime.h>
#include <cstdint>

#define H     64
#define F     5
#define BS    32     // samples per CTA; grid = 4096/32 = 128, single wave
#define TPB   256
#define RB    128

// word-indexed SMEM: two parities of B-fragments, then final-h buffer
#define PWORDS 4752              // per-parity: BHI 2112 | BLO 2112 | BXH 264 | BXL 264
#define BHI_W  0
#define BLO_W  2112
#define BXH_W  4224
#define BXL_W  4488
#define HFIN_W (2 * PWORDS)      // 64 x 33 floats
#define TOTW   (HFIN_W + 64 * 33)

__device__ float g_rank_part[RB];
__device__ float g_reg_part[2];

__device__ __forceinline__ float tanh_hw(float x) {
    float y; asm("tanh.approx.f32 %0, %1;" : "=f"(y) : "f"(x)); return y;
}
__device__ __forceinline__ float sig_hw(float x) {
    return fmaf(tanh_hw(0.5f * x), 0.5f, 0.5f);
}
__device__ __forceinline__ uint32_t tf32u(float x) {
    uint32_t u; asm("cvt.rna.tf32.f32 %0, %1;" : "=r"(u) : "f"(x)); return u;
}
__device__ __forceinline__ void mma8(float* c, const uint32_t* a, const uint32_t* b) {
    asm volatile("mma.sync.aligned.m16n8k8.row.col.f32.tf32.tf32.f32 "
        "{%0,%1,%2,%3}, {%4,%5,%6,%7}, {%8,%9}, {%0,%1,%2,%3};"
        : "+f"(c[0]), "+f"(c[1]), "+f"(c[2]), "+f"(c[3])
        : "r"(a[0]), "r"(a[1]), "r"(a[2]), "r"(a[3]), "r"(b[0]), "r"(b[1]));
}

__global__ __launch_bounds__(TPB, 1)
void lstm_kernel(const float* __restrict__ feature,
                 const float* __restrict__ Wih, const float* __restrict__ Whh,
                 const float* __restrict__ bih, const float* __restrict__ bhh,
                 const float* __restrict__ Wd,  const float* __restrict__ bd,
                 float* __restrict__ pred, int N, int T)
{
    __shared__ uint32_t smw[TOTW];

    const int tid = threadIdx.x, w = tid >> 5, lane = tid & 31;
    const int g   = lane >> 2,  tq = lane & 3;
    const int u   = 8 * w + g;                 // this thread's hidden unit
    const int n0  = blockIdx.x * BS;

    // ---- A fragments with gate-permuted rows ----
    // band row (gate*8 + g) = Whh row (gate*64 + u):
    //   mt=0 -> rows (u, 64+u)   = gates i, f
    //   mt=1 -> rows (128+u, 192+u) = gates g, o
    uint32_t aHi[2][8][4], aLo[2][8][4], AE1[2][4], AE2[2][4];
#pragma unroll
    for (int mt = 0; mt < 2; mt++) {
        const int rA = (2 * mt) * H + u, rB = (2 * mt + 1) * H + u;
#pragma unroll
        for (int kc = 0; kc < 8; kc++) {
            const int k0 = 8 * kc + tq, k1 = k0 + 4;
            float v0 = Whh[rA * H + k0], v1 = Whh[rB * H + k0];
            float v2 = Whh[rA * H + k1], v3 = Whh[rB * H + k1];
            uint32_t h0 = tf32u(v0), h1 = tf32u(v1), h2 = tf32u(v2), h3 = tf32u(v3);
            aHi[mt][kc][0] = h0; aHi[mt][kc][1] = h1; aHi[mt][kc][2] = h2; aHi[mt][kc][3] = h3;
            aLo[mt][kc][0] = tf32u(v0 - __uint_as_float(h0));
            aLo[mt][kc][1] = tf32u(v1 - __uint_as_float(h1));
            aLo[mt][kc][2] = tf32u(v2 - __uint_as_float(h2));
            aLo[mt][kc][3] = tf32u(v3 - __uint_as_float(h3));
        }
        // ext chunk cols: 0-4 = Wih, 5 = bias, 6-7 = 0
        float e0 = Wih[rA * F + tq], e1 = Wih[rB * F + tq];
        float e2 = 0.f, e3 = 0.f;
        if (tq == 0)      { e2 = Wih[rA * F + 4];   e3 = Wih[rB * F + 4]; }
        else if (tq == 1) { e2 = bih[rA] + bhh[rA]; e3 = bih[rB] + bhh[rB]; }
        uint32_t q0 = tf32u(e0), q1 = tf32u(e1), q2 = tf32u(e2), q3 = tf32u(e3);
        AE1[mt][0] = q0; AE1[mt][1] = q1; AE1[mt][2] = q2; AE1[mt][3] = q3;
        AE2[mt][0] = tf32u(e0 - __uint_as_float(q0));
        AE2[mt][1] = tf32u(e1 - __uint_as_float(q1));
        AE2[mt][2] = tf32u(e2 - __uint_as_float(q2));
        AE2[mt][3] = tf32u(e3 - __uint_as_float(q3));
    }

    // x staging role: thread tid < 160 handles (sample sx, feature fx)
    const int  sx  = tid / 5, fx = tid - 5 * sx;
    const bool isx = tid < BS * F;
    const uint32_t bxOff = (uint32_t)(((sx >> 3) * 64) + (sx & 7) * 8 + (fx & 3) * 2 + (fx >> 2));

    // h writer base: element (u, s): word = (u>>3)*264 + (s>>3)*64 + (u&3)*2 + ((u>>2)&1) + 8*(s&7)
    const uint32_t whW = (uint32_t)((u >> 3) * 264 + (u & 3) * 2 + ((u >> 2) & 1));

    // ---- init: zero everything; bias-ones in both parities; x(0) in parity 0 ----
    for (int i = tid; i < TOTW; i += TPB) smw[i] = 0;
    __syncthreads();
    if (tid < 64) {   // ones at k=5 of ext-hi: word BXH + nt*64 + 8*gg + 3
        int p = tid >> 5, rem = tid & 31, nt = rem >> 3, gg = rem & 7;
        smw[p * PWORDS + BXH_W + nt * 64 + 8 * gg + 3] = __float_as_uint(1.0f);
    }
    if (isx && n0 + sx < N) {
        float xv = feature[(size_t)(n0 + sx) * T * F + fx];
        uint32_t hb = tf32u(xv);
        smw[BXH_W + bxOff] = hb;
        smw[BXL_W + bxOff] = tf32u(xv - __uint_as_float(hb));
    }
    __syncthreads();

    float c_reg[8];   // c for (nt, j): index nt*2 + j, sample 8nt + 2tq + j
#pragma unroll
    for (int i = 0; i < 8; i++) c_reg[i] = 0.f;

    for (int t = 0; t < T; t++) {
        const int p = t & 1, pn = p ^ 1;
        const uint32_t pw = (uint32_t)p * PWORDS, pnw = (uint32_t)pn * PWORDS;

        float xv = 0.f;
        const bool xok = isx && (t + 1 < T) && (n0 + sx < N);
        if (xok) xv = feature[(size_t)(n0 + sx) * T * F + (size_t)(t + 1) * F + fx];

        float C[2][4][4];
#pragma unroll
        for (int mt = 0; mt < 2; mt++)
#pragma unroll
            for (int nt = 0; nt < 4; nt++)
#pragma unroll
                for (int q = 0; q < 4; q++) C[mt][nt][q] = 0.f;

        const uint2* pBH = (const uint2*)(smw + pw + BHI_W);
        const uint2* pBL = (const uint2*)(smw + pw + BLO_W);
        const uint2* pXH = (const uint2*)(smw + pw + BXH_W);
        const uint2* pXL = (const uint2*)(smw + pw + BXL_W);

        // ---- 3xTF32 mainloop over K ----
#pragma unroll
        for (int kc = 0; kc < 8; kc++) {
            uint2 bh[4], bl[4];
#pragma unroll
            for (int nt = 0; nt < 4; nt++) bh[nt] = pBH[kc * 132 + nt * 32 + lane];
#pragma unroll
            for (int mt = 0; mt < 2; mt++)
#pragma unroll
                for (int nt = 0; nt < 4; nt++)
                    mma8(C[mt][nt], aHi[mt][kc], (const uint32_t*)&bh[nt]);
#pragma unroll
            for (int nt = 0; nt < 4; nt++) bl[nt] = pBL[kc * 132 + nt * 32 + lane];
#pragma unroll
            for (int mt = 0; mt < 2; mt++)
#pragma unroll
                for (int nt = 0; nt < 4; nt++)
                    mma8(C[mt][nt], aLo[mt][kc], (const uint32_t*)&bh[nt]);
#pragma unroll
            for (int mt = 0; mt < 2; mt++)
#pragma unroll
                for (int nt = 0; nt < 4; nt++)
                    mma8(C[mt][nt], aHi[mt][kc], (const uint32_t*)&bl[nt]);
        }
        // ---- ext chunks: Wih·x + bias ----
        {
            uint2 xh[4], xl[4];
#pragma unroll
            for (int nt = 0; nt < 4; nt++) { xh[nt] = pXH[nt * 32 + lane]; xl[nt] = pXL[nt * 32 + lane]; }
#pragma unroll
            for (int mt = 0; mt < 2; mt++)
#pragma unroll
                for (int nt = 0; nt < 4; nt++) {
                    mma8(C[mt][nt], AE1[mt], (const uint32_t*)&xh[nt]);
                    mma8(C[mt][nt], AE2[mt], (const uint32_t*)&xh[nt]);
                    mma8(C[mt][nt], AE1[mt], (const uint32_t*)&xl[nt]);
                }
        }

        // ---- epilogue: all 4 gates already in C regs (i,f | g,o) ----
        if (t < T - 1) {
            uint32_t* dH = smw + pnw + BHI_W + whW;
            uint32_t* dL = smw + pnw + BLO_W + whW;
#pragma unroll
            for (int nt = 0; nt < 4; nt++)
#pragma unroll
                for (int j = 0; j < 2; j++) {
                    float ig = sig_hw(C[0][nt][j]);
                    float fg = sig_hw(C[0][nt][2 + j]);
                    float gg = tanh_hw(C[1][nt][j]);
                    float og = sig_hw(C[1][nt][2 + j]);
                    float c  = fg * c_reg[nt * 2 + j] + ig * gg;
                    c_reg[nt * 2 + j] = c;
                    float hv = og * tanh_hw(c);
                    uint32_t hb = tf32u(hv);
                    const uint32_t off = (uint32_t)(nt * 64 + 8 * (2 * tq + j));
                    dH[off] = hb;
                    dL[off] = tf32u(hv - __uint_as_float(hb));
                }
        } else {
            float* hf = (float*)(smw + HFIN_W);
#pragma unroll
            for (int nt = 0; nt < 4; nt++)
#pragma unroll
                for (int j = 0; j < 2; j++) {
                    float ig = sig_hw(C[0][nt][j]);
                    float fg = sig_hw(C[0][nt][2 + j]);
                    float gg = tanh_hw(C[1][nt][j]);
                    float og = sig_hw(C[1][nt][2 + j]);
                    float c  = fg * c_reg[nt * 2 + j] + ig * gg;
                    hf[u * 33 + 8 * nt + 2 * tq + j] = og * tanh_hw(c);
                }
        }
        if (xok) {
            uint32_t hb = tf32u(xv);
            smw[pnw + BXH_W + bxOff] = hb;
            smw[pnw + BXL_W + bxOff] = tf32u(xv - __uint_as_float(hb));
        }
        __syncthreads();
    }

    // ---- head: pred = leaky_relu(h . Wd + bd, 0.2); warp w -> samples 4w..4w+3
    const float* hf = (const float*)(smw + HFIN_W);
#pragma unroll
    for (int sl = 0; sl < 4; sl++) {
        const int s = 4 * w + sl;
        float pv = hf[lane * 33 + s] * Wd[lane]
                 + hf[(lane + 32) * 33 + s] * Wd[lane + 32];
#pragma unroll
        for (int off = 16; off; off >>= 1) pv += __shfl_down_sync(0xffffffffu, pv, off);
        if (lane == 0 && n0 + s < N) {
            pv += bd[0];
            pv = pv > 0.f ? pv : 0.2f * pv;
            pred[n0 + s] = pv;
        }
    }
}

// Pairwise rank loss partials + masked MSE partials (deterministic, no atomics).
__global__ void pair_kernel(const float* __restrict__ pred, const float* __restrict__ ret,
                            const unsigned* __restrict__ mask, int N)
{
    __shared__ float p_sm[4096];
    __shared__ float t_sm[4096];
    __shared__ unsigned char m_sm[4096];
    __shared__ float red[256];
    const int tid = threadIdx.x;

    for (int n = tid; n < N; n += blockDim.x) {
        p_sm[n] = pred[n];
        t_sm[n] = ret[n];
        m_sm[n] = (mask[n] != 0u) ? 1 : 0;
    }
    __syncthreads();

    float rsum = 0.f;
    for (int i = blockIdx.x; i < N; i += gridDim.x) {
        if (!m_sm[i]) continue;
        float pi = p_sm[i], gi = t_sm[i];
        for (int j = tid; j < N; j += blockDim.x) {
            float v = -(p_sm[j] - pi) * (t_sm[j] - gi);
            v = fmaxf(v, 0.f);
            rsum += v * (float)m_sm[j];
        }
    }
    red[tid] = rsum;
    __syncthreads();
    for (int s = 128; s; s >>= 1) { if (tid < s) red[tid] += red[tid + s]; __syncthreads(); }
    if (tid == 0) g_rank_part[blockIdx.x] = red[0];

    if (blockIdx.x == 0) {
        float ssq = 0.f, sm = 0.f;
        for (int n = tid; n < N; n += blockDim.x) {
            float m = (float)m_sm[n];
            float d = p_sm[n] - t_sm[n];
            ssq += d * d * m;
            sm  += m;
        }
        __syncthreads();
        red[tid] = ssq; __syncthreads();
        for (int s = 128; s; s >>= 1) { if (tid < s) red[tid] += red[tid + s]; __syncthreads(); }
        if (tid == 0) g_reg_part[0] = red[0];
        __syncthreads();
        red[tid] = sm; __syncthreads();
        for (int s = 128; s; s >>= 1) { if (tid < s) red[tid] += red[tid + s]; __syncthreads(); }
        if (tid == 0) g_reg_part[1] = red[0];
    }
}

__global__ void finalize_kernel(float* __restrict__ out, int N)
{
    if (threadIdx.x == 0 && blockIdx.x == 0) {
        float srank = 0.f;
        for (int b = 0; b < RB; b++) srank += g_rank_part[b];
        float reg  = g_reg_part[0] / (g_reg_part[1] + 1e-8f);
        float rank = srank / ((float)N * (float)N);
        out[N]     = reg + rank;
        out[N + 1] = reg;
        out[N + 2] = rank;
    }
}

extern "C" void kernel_launch(void* const* d_in, const int* in_sizes, int n_in,
                              void* d_out, int out_size)
{
    const float*    feature = (const float*)d_in[0];
    const float*    ret     = (const float*)d_in[1];
    const unsigned* mask    = (const unsigned*)d_in[2];
    const float*    Wih     = (const float*)d_in[3];
    const float*    Whh     = (const float*)d_in[4];
    const float*    bih     = (const float*)d_in[5];
    const float*    bhh     = (const float*)d_in[6];
    const float*    Wd      = (const float*)d_in[7];
    const float*    bd      = (const float*)d_in[8];
    float* out = (float*)d_out;

    const int N = in_sizes[1];                 // 4096
    const int T = in_sizes[0] / (N * F);       // 512

    const int grid = (N + BS - 1) / BS;        // 128
    lstm_kernel<<<grid, TPB>>>(feature, Wih, Whh, bih, bhh, Wd, bd, out, N, T);
    pair_kernel<<<RB, 256>>>(out, ret, mask, N);
    finalize_kernel<<<1, 32>>>(out, N);
}

// round 16
// speedup vs baseline: 3.9452x; 1.4900x over previous
#include <cuda_runtime.h>
#include <cuda_fp16.h>
#include <cstdint>

#define H     64
#define F     5
#define BS    32     // samples per CTA; grid = 4096/32 = 128, single wave
#define TPB   256
#define RB    128
#define SLO   (1.f / 2048.f)   // lo-pass scale fixup

// word-indexed SMEM, per parity: BH 1056 | BL 1056 | X1 264 | X2 264
#define BH_W   0
#define BL_W   1056
#define X1_W   2112
#define X2_W   2376
#define PW     2640
#define HFIN_W (2 * PW)          // 64 x 33 floats
#define TOTW   (HFIN_W + 64 * 33)

__device__ float g_rank_part[RB];
__device__ float g_reg_part[2];

__device__ __forceinline__ float tanh_hw(float x) {
    float y; asm("tanh.approx.f32 %0, %1;" : "=f"(y) : "f"(x)); return y;
}
__device__ __forceinline__ float sig_hw(float x) {
    return fmaf(tanh_hw(0.5f * x), 0.5f, 0.5f);
}
__device__ __forceinline__ uint32_t packh2(__half a, __half b) {   // a -> low (even k)
    __half2 h = __halves2half2(a, b);
    return *(uint32_t*)&h;
}
__device__ __forceinline__ void mma16(float* c, const uint32_t* a, const uint32_t* b) {
    asm volatile("mma.sync.aligned.m16n8k16.row.col.f32.f16.f16.f32 "
        "{%0,%1,%2,%3}, {%4,%5,%6,%7}, {%8,%9}, {%0,%1,%2,%3};"
        : "+f"(c[0]), "+f"(c[1]), "+f"(c[2]), "+f"(c[3])
        : "r"(a[0]), "r"(a[1]), "r"(a[2]), "r"(a[3]), "r"(b[0]), "r"(b[1]));
}
// halfword index of B element (k, sample s) within a chunk region starting at baseW
__device__ __forceinline__ int hw_idx(int baseW, int k, int s) {
    int kk = k & 15;
    int r = (kk >> 3) & 1, tqt = (kk >> 1) & 3, i = kk & 1;
    int word = baseW + ((k >> 4) * 4 + (s >> 3)) * 66 + ((s & 7) * 4 + tqt) * 2 + r;
    return word * 2 + i;
}

__global__ __launch_bounds__(TPB, 1)
void lstm_kernel(const float* __restrict__ feature,
                 const float* __restrict__ Wih, const float* __restrict__ Whh,
                 const float* __restrict__ bih, const float* __restrict__ bhh,
                 const float* __restrict__ Wd,  const float* __restrict__ bd,
                 float* __restrict__ pred, int N, int T)
{
    __shared__ uint32_t smw[TOTW];
    __half* hp = (__half*)smw;

    const int tid = threadIdx.x, w = tid >> 5, lane = tid & 31;
    const int g   = lane >> 2,  tq = lane & 3;
    const int u   = 8 * w + g;                 // this thread's hidden unit
    const int n0  = blockIdx.x * BS;

    // ---- A fragments (fp16 hi + scaled-lo), gate-permuted rows ----
    // mt=0 -> Whh rows (u, 64+u) = gates i,f ; mt=1 -> (128+u, 192+u) = g,o
    uint32_t aHi[2][4][4], aLo[2][4][4], AE1[2][4], AE2[2][4];
#pragma unroll
    for (int mt = 0; mt < 2; mt++) {
        const int rA = (2 * mt) * H + u, rB = (2 * mt + 1) * H + u;
#pragma unroll
        for (int kc = 0; kc < 4; kc++) {
#pragma unroll
            for (int half8 = 0; half8 < 2; half8++) {
                const int k0 = 16 * kc + 2 * tq + 8 * half8;
#pragma unroll
                for (int rr = 0; rr < 2; rr++) {
                    const int row = rr ? rB : rA;
                    float w0 = Whh[row * H + k0], w1 = Whh[row * H + k0 + 1];
                    __half h0 = __float2half_rn(w0), h1 = __float2half_rn(w1);
                    __half l0 = __float2half_rn((w0 - __half2float(h0)) * 2048.f);
                    __half l1 = __float2half_rn((w1 - __half2float(h1)) * 2048.f);
                    aHi[mt][kc][2 * half8 + rr] = packh2(h0, h1);
                    aLo[mt][kc][2 * half8 + rr] = packh2(l0, l1);
                }
            }
        }
        // ext A: AE1 k0-4 = Wih_hi (others 0); AE2 k0-4 = Wih_lo', k5-9 = Wih_hi
        auto ev1 = [&](int row, int k) -> __half {
            if (k < 5) return __float2half_rn(Wih[row * F + k]);
            return __float2half_rn(0.f);
        };
        auto ev2 = [&](int row, int k) -> __half {
            if (k < 5) {
                float wv = Wih[row * F + k];
                __half hh = __float2half_rn(wv);
                return __float2half_rn((wv - __half2float(hh)) * 2048.f);
            }
            if (k < 10) return __float2half_rn(Wih[row * F + (k - 5)]);
            return __float2half_rn(0.f);
        };
#pragma unroll
        for (int half8 = 0; half8 < 2; half8++) {
            const int k0 = 2 * tq + 8 * half8;
#pragma unroll
            for (int rr = 0; rr < 2; rr++) {
                const int row = rr ? rB : rA;
                AE1[mt][2 * half8 + rr] = packh2(ev1(row, k0), ev1(row, k0 + 1));
                AE2[mt][2 * half8 + rr] = packh2(ev2(row, k0), ev2(row, k0 + 1));
            }
        }
    }
    // per-thread gate biases (exact fp32, added in epilogue)
    float bi[4];
#pragma unroll
    for (int gg = 0; gg < 4; gg++) bi[gg] = bih[gg * H + u] + bhh[gg * H + u];

    // x staging role
    const int  sx  = tid / 5, fx = tid - 5 * sx;
    const bool isx = tid < BS * F;

    // ---- init: zero all; x(0) into parity 0 ----
    for (int i = tid; i < TOTW; i += TPB) smw[i] = 0;
    __syncthreads();
    if (isx && n0 + sx < N) {
        float xv = feature[(size_t)(n0 + sx) * T * F + fx];
        __half xh = __float2half_rn(xv);
        hp[hw_idx(X1_W, fx, sx)]     = xh;
        hp[hw_idx(X2_W, fx, sx)]     = __float2half_rn((xv - __half2float(xh)) * 2048.f);
        hp[hw_idx(X2_W, 5 + fx, sx)] = xh;
    }
    __syncthreads();

    float c_reg[8];   // cell state for (nt, j): sample 8nt + 2tq + j
#pragma unroll
    for (int i = 0; i < 8; i++) c_reg[i] = 0.f;

    for (int t = 0; t < T; t++) {
        const int p = t & 1, pn = p ^ 1;
        const int pw = p * PW, pnw = pn * PW;

        float xv = 0.f;
        const bool xok = isx && (t + 1 < T) && (n0 + sx < N);
        if (xok) xv = feature[(size_t)(n0 + sx) * T * F + (size_t)(t + 1) * F + fx];

        float C1[2][4][4], C2[2][4][4];
#pragma unroll
        for (int mt = 0; mt < 2; mt++)
#pragma unroll
            for (int nt = 0; nt < 4; nt++)
#pragma unroll
                for (int q = 0; q < 4; q++) { C1[mt][nt][q] = 0.f; C2[mt][nt][q] = 0.f; }

        const uint2* pBH = (const uint2*)(smw + pw + BH_W);
        const uint2* pBL = (const uint2*)(smw + pw + BL_W);
        const uint2* pX1 = (const uint2*)(smw + pw + X1_W);
        const uint2* pX2 = (const uint2*)(smw + pw + X2_W);

        // ---- fp16x3 mainloop: C1 += Whi*Hhi ; C2 += Wlo'*Hhi + Whi*Hlo' ----
#pragma unroll
        for (int kc = 0; kc < 4; kc++) {
            uint2 bh[4], bl[4];
#pragma unroll
            for (int nt = 0; nt < 4; nt++) bh[nt] = pBH[(kc * 4 + nt) * 33 + lane];
#pragma unroll
            for (int mt = 0; mt < 2; mt++)
#pragma unroll
                for (int nt = 0; nt < 4; nt++)
                    mma16(C1[mt][nt], aHi[mt][kc], (const uint32_t*)&bh[nt]);
#pragma unroll
            for (int nt = 0; nt < 4; nt++) bl[nt] = pBL[(kc * 4 + nt) * 33 + lane];
#pragma unroll
            for (int mt = 0; mt < 2; mt++)
#pragma unroll
                for (int nt = 0; nt < 4; nt++)
                    mma16(C2[mt][nt], aLo[mt][kc], (const uint32_t*)&bh[nt]);
#pragma unroll
            for (int mt = 0; mt < 2; mt++)
#pragma unroll
                for (int nt = 0; nt < 4; nt++)
                    mma16(C2[mt][nt], aHi[mt][kc], (const uint32_t*)&bl[nt]);
        }
        // ---- ext: C1 += Whi*xhi ; C2 += Whi*xlo' + Wlo'*xhi ----
        {
            uint2 x1[4], x2[4];
#pragma unroll
            for (int nt = 0; nt < 4; nt++) { x1[nt] = pX1[nt * 33 + lane]; x2[nt] = pX2[nt * 33 + lane]; }
#pragma unroll
            for (int mt = 0; mt < 2; mt++)
#pragma unroll
                for (int nt = 0; nt < 4; nt++) {
                    mma16(C1[mt][nt], AE1[mt], (const uint32_t*)&x1[nt]);
                    mma16(C2[mt][nt], AE2[mt], (const uint32_t*)&x2[nt]);
                }
        }

        // ---- epilogue: gates in regs; pre = bias + C1 + SLO*C2 ----
        if (t < T - 1) {
#pragma unroll
            for (int nt = 0; nt < 4; nt++)
#pragma unroll
                for (int j = 0; j < 2; j++) {
                    float ig = sig_hw(bi[0] + fmaf(SLO, C2[0][nt][j],     C1[0][nt][j]));
                    float fg = sig_hw(bi[1] + fmaf(SLO, C2[0][nt][2 + j], C1[0][nt][2 + j]));
                    float gg = tanh_hw(bi[2] + fmaf(SLO, C2[1][nt][j],    C1[1][nt][j]));
                    float og = sig_hw(bi[3] + fmaf(SLO, C2[1][nt][2 + j], C1[1][nt][2 + j]));
                    float c  = fg * c_reg[nt * 2 + j] + ig * gg;
                    c_reg[nt * 2 + j] = c;
                    float hv = og * tanh_hw(c);
                    const int s = 8 * nt + 2 * tq + j;
                    __half hh = __float2half_rn(hv);
                    hp[pnw * 2 + hw_idx(BH_W, u, s)] = hh;
                    hp[pnw * 2 + hw_idx(BL_W, u, s)] =
                        __float2half_rn((hv - __half2float(hh)) * 2048.f);
                }
        } else {
            float* hf = (float*)(smw + HFIN_W);
#pragma unroll
            for (int nt = 0; nt < 4; nt++)
#pragma unroll
                for (int j = 0; j < 2; j++) {
                    float ig = sig_hw(bi[0] + fmaf(SLO, C2[0][nt][j],     C1[0][nt][j]));
                    float fg = sig_hw(bi[1] + fmaf(SLO, C2[0][nt][2 + j], C1[0][nt][2 + j]));
                    float gg = tanh_hw(bi[2] + fmaf(SLO, C2[1][nt][j],    C1[1][nt][j]));
                    float og = sig_hw(bi[3] + fmaf(SLO, C2[1][nt][2 + j], C1[1][nt][2 + j]));
                    float c  = fg * c_reg[nt * 2 + j] + ig * gg;
                    hf[u * 33 + 8 * nt + 2 * tq + j] = og * tanh_hw(c);
                }
        }
        if (xok) {
            __half xh = __float2half_rn(xv);
            hp[pnw * 2 + hw_idx(X1_W, fx, sx)]     = xh;
            hp[pnw * 2 + hw_idx(X2_W, fx, sx)]     =
                __float2half_rn((xv - __half2float(xh)) * 2048.f);
            hp[pnw * 2 + hw_idx(X2_W, 5 + fx, sx)] = xh;
        }
        __syncthreads();
    }

    // ---- head: pred = leaky_relu(h . Wd + bd, 0.2); warp w -> samples 4w..4w+3
    const float* hf = (const float*)(smw + HFIN_W);
#pragma unroll
    for (int sl = 0; sl < 4; sl++) {
        const int s = 4 * w + sl;
        float pv = hf[lane * 33 + s] * Wd[lane]
                 + hf[(lane + 32) * 33 + s] * Wd[lane + 32];
#pragma unroll
        for (int off = 16; off; off >>= 1) pv += __shfl_down_sync(0xffffffffu, pv, off);
        if (lane == 0 && n0 + s < N) {
            pv += bd[0];
            pv = pv > 0.f ? pv : 0.2f * pv;
            pred[n0 + s] = pv;
        }
    }
}

// Pairwise rank loss partials + masked MSE partials (deterministic, no atomics).
__global__ void pair_kernel(const float* __restrict__ pred, const float* __restrict__ ret,
                            const unsigned* __restrict__ mask, int N)
{
    __shared__ float p_sm[4096];
    __shared__ float t_sm[4096];
    __shared__ unsigned char m_sm[4096];
    __shared__ float red[256];
    const int tid = threadIdx.x;

    for (int n = tid; n < N; n += blockDim.x) {
        p_sm[n] = pred[n];
        t_sm[n] = ret[n];
        m_sm[n] = (mask[n] != 0u) ? 1 : 0;
    }
    __syncthreads();

    float rsum = 0.f;
    for (int i = blockIdx.x; i < N; i += gridDim.x) {
        if (!m_sm[i]) continue;
        float pi = p_sm[i], gi = t_sm[i];
        for (int j = tid; j < N; j += blockDim.x) {
            float v = -(p_sm[j] - pi) * (t_sm[j] - gi);
            v = fmaxf(v, 0.f);
            rsum += v * (float)m_sm[j];
        }
    }
    red[tid] = rsum;
    __syncthreads();
    for (int s = 128; s; s >>= 1) { if (tid < s) red[tid] += red[tid + s]; __syncthreads(); }
    if (tid == 0) g_rank_part[blockIdx.x] = red[0];

    if (blockIdx.x == 0) {
        float ssq = 0.f, sm = 0.f;
        for (int n = tid; n < N; n += blockDim.x) {
            float m = (float)m_sm[n];
            float d = p_sm[n] - t_sm[n];
            ssq += d * d * m;
            sm  += m;
        }
        __syncthreads();
        red[tid] = ssq; __syncthreads();
        for (int s = 128; s; s >>= 1) { if (tid < s) red[tid] += red[tid + s]; __syncthreads(); }
        if (tid == 0) g_reg_part[0] = red[0];
        __syncthreads();
        red[tid] = sm; __syncthreads();
        for (int s = 128; s; s >>= 1) { if (tid < s) red[tid] += red[tid + s]; __syncthreads(); }
        if (tid == 0) g_reg_part[1] = red[0];
    }
}

__global__ void finalize_kernel(float* __restrict__ out, int N)
{
    if (threadIdx.x == 0 && blockIdx.x == 0) {
        float srank = 0.f;
        for (int b = 0; b < RB; b++) srank += g_rank_part[b];
        float reg  = g_reg_part[0] / (g_reg_part[1] + 1e-8f);
        float rank = srank / ((float)N * (float)N);
        out[N]     = reg + rank;
        out[N + 1] = reg;
        out[N + 2] = rank;
    }
}

extern "C" void kernel_launch(void* const* d_in, const int* in_sizes, int n_in,
                              void* d_out, int out_size)
{
    const float*    feature = (const float*)d_in[0];
    const float*    ret     = (const float*)d_in[1];
    const unsigned* mask    = (const unsigned*)d_in[2];
    const float*    Wih     = (const float*)d_in[3];
    const float*    Whh     = (const float*)d_in[4];
    const float*    bih     = (const float*)d_in[5];
    const float*    bhh     = (const float*)d_in[6];
    const float*    Wd      = (const float*)d_in[7];
    const float*    bd      = (const float*)d_in[8];
    float* out = (float*)d_out;

    const int N = in_sizes[1];                 // 4096
    const int T = in_sizes[0] / (N * F);       // 512

    const int grid = (N + BS - 1) / BS;        // 128
    lstm_kernel<<<grid, TPB>>>(feature, Wih, Whh, bih, bhh, Wd, bd, out, N, T);
    pair_kernel<<<RB, 256>>>(out, ret, mask, N);
    finalize_kernel<<<1, 32>>>(out, N);
}